// round 1
// baseline (speedup 1.0000x reference)
#include <cuda_runtime.h>
#include <math.h>

#define NHEADS 16
#define SEQ    2048
#define HD     64
#define EMB    1024
#define LHD    (SEQ*HD)        // 131072 per-head elems
#define TOT    (NHEADS*SEQ*HD) // 2097152

// ---------------- scratch (device globals; no allocations) ----------------
__device__ float g_Q[TOT];
__device__ float g_K[TOT];
__device__ float g_V[TOT];
__device__ float g_Kn[TOT];
__device__ float g_u[TOT];
__device__ float g_u2[TOT];
__device__ float g_Vp[TOT];
__device__ float g_attn[SEQ*EMB];
__device__ float g_csum[NHEADS*HD];

// ---------------- SGEMM: C = A(MxK) @ B(KxN) + bias ----------------
// MODE 0: write head-split  out[h][m][d]  with h=n/64, d=n%64
// MODE 1: write row-major   out[m][n]
// blockIdx.z selects one of up to 3 (B,bias,C) triples (fused QKV).
template<int MODE>
__global__ __launch_bounds__(256) void gemm_kernel(
    const float* __restrict__ A,
    const float* __restrict__ B0, const float* __restrict__ bias0, float* __restrict__ C0,
    const float* __restrict__ B1, const float* __restrict__ bias1, float* __restrict__ C1,
    const float* __restrict__ B2, const float* __restrict__ bias2, float* __restrict__ C2,
    int M, int N, int K)
{
    const float* B; const float* bias; float* C;
    if (blockIdx.z == 0)      { B = B0; bias = bias0; C = C0; }
    else if (blockIdx.z == 1) { B = B1; bias = bias1; C = C1; }
    else                      { B = B2; bias = bias2; C = C2; }

    __shared__ float As[16*128];   // k-major (transposed on load)
    __shared__ float Bs[16*128];   // k-major (natural)

    const int tid = threadIdx.x;
    const int m0 = blockIdx.y * 128, n0 = blockIdx.x * 128;
    const int ty = tid >> 4, tx = tid & 15;

    float acc[8][8];
    #pragma unroll
    for (int i = 0; i < 8; i++)
        #pragma unroll
        for (int j = 0; j < 8; j++) acc[i][j] = 0.f;

    for (int k0 = 0; k0 < K; k0 += 16) {
        // load A tile 128x16 (transpose into As[k][m])
        #pragma unroll
        for (int i = 0; i < 2; i++) {
            int idx = tid + i * 256;           // 0..511
            int row = idx >> 2, q = idx & 3;   // row 0..127, q 0..3
            float4 a4 = *(const float4*)(A + (size_t)(m0 + row) * K + k0 + q * 4);
            As[(q*4+0)*128 + row] = a4.x;
            As[(q*4+1)*128 + row] = a4.y;
            As[(q*4+2)*128 + row] = a4.z;
            As[(q*4+3)*128 + row] = a4.w;
        }
        // load B tile 16x128
        #pragma unroll
        for (int i = 0; i < 2; i++) {
            int idx = tid + i * 256;
            int row = idx >> 5, q = idx & 31;  // row 0..15, q 0..31
            *(float4*)(Bs + row * 128 + q * 4) =
                *(const float4*)(B + (size_t)(k0 + row) * N + n0 + q * 4);
        }
        __syncthreads();
        #pragma unroll
        for (int k = 0; k < 16; k++) {
            float a[8], b[8];
            *(float4*)(a)     = *(float4*)(As + k*128 + ty*8);
            *(float4*)(a + 4) = *(float4*)(As + k*128 + ty*8 + 4);
            *(float4*)(b)     = *(float4*)(Bs + k*128 + tx*8);
            *(float4*)(b + 4) = *(float4*)(Bs + k*128 + tx*8 + 4);
            #pragma unroll
            for (int i = 0; i < 8; i++)
                #pragma unroll
                for (int j = 0; j < 8; j++) acc[i][j] = fmaf(a[i], b[j], acc[i][j]);
        }
        __syncthreads();
    }

    const int ncol = n0 + tx * 8;   // 8 consecutive cols, stays within one 64-block
    float bv[8];
    #pragma unroll
    for (int j = 0; j < 8; j++) bv[j] = bias[ncol + j];

    #pragma unroll
    for (int i = 0; i < 8; i++) {
        int m = m0 + ty * 8 + i;
        float o[8];
        #pragma unroll
        for (int j = 0; j < 8; j++) o[j] = acc[i][j] + bv[j];
        if (MODE == 0) {
            int h = ncol >> 6, d = ncol & 63;
            float* dst = C + ((size_t)h * SEQ + m) * HD + d;
            *(float4*)dst       = *(float4*)(o);
            *(float4*)(dst + 4) = *(float4*)(o + 4);
        } else {
            float* dst = C + (size_t)m * N + ncol;
            *(float4*)dst       = *(float4*)(o);
            *(float4*)(dst + 4) = *(float4*)(o + 4);
        }
    }
}

// ---------------- K row-normalize: Kn = K / max(||K||,1e-6) ----------------
__global__ __launch_bounds__(256) void knorm_kernel(const float* __restrict__ K,
                                                    float* __restrict__ Kn)
{
    int row  = blockIdx.x * 8 + (threadIdx.x >> 5);
    int lane = threadIdx.x & 31;
    const float* kr = K + (size_t)row * HD;
    float v0 = kr[lane], v1 = kr[lane + 32];
    float ss = v0 * v0 + v1 * v1;
    #pragma unroll
    for (int o = 16; o; o >>= 1) ss += __shfl_xor_sync(0xffffffffu, ss, o);
    float inv = 1.f / fmaxf(sqrtf(ss), 1e-6f);
    Kn[(size_t)row * HD + lane]      = v0 * inv;
    Kn[(size_t)row * HD + lane + 32] = v1 * inv;
}

// ---------------- column sums per head: cs[h][d] = sum_l Vin[h][l][d] -------
__global__ __launch_bounds__(256) void colsum_kernel(const float* __restrict__ Vin,
                                                     float* __restrict__ cs)
{
    int h = blockIdx.x;
    int d = threadIdx.x & 63;
    int s = threadIdx.x >> 6;               // 4 strips
    const float* base = Vin + (size_t)h * LHD;
    float acc = 0.f;
    for (int l = s; l < SEQ; l += 4) acc += base[(size_t)l * HD + d];
    __shared__ float red[256];
    red[threadIdx.x] = acc;
    __syncthreads();
    if (s == 0) cs[h * HD + d] = red[d] + red[64 + d] + red[128 + d] + red[192 + d];
}

// ---------------- elementwise: dst = c*src  /  dst += c*src -----------------
__global__ __launch_bounds__(256) void scale_kernel(float* __restrict__ dst,
                                                    const float* __restrict__ src, float c)
{
    int i = blockIdx.x * 256 + threadIdx.x;   // float4 index
    float4 v = ((const float4*)src)[i];
    v.x *= c; v.y *= c; v.z *= c; v.w *= c;
    ((float4*)dst)[i] = v;
}
__global__ __launch_bounds__(256) void axpy_kernel(float* __restrict__ dst,
                                                   const float* __restrict__ src, float c)
{
    int i = blockIdx.x * 256 + threadIdx.x;
    float4 v = ((const float4*)src)[i];
    float4 d = ((float4*)dst)[i];
    d.x = fmaf(c, v.x, d.x); d.y = fmaf(c, v.y, d.y);
    d.z = fmaf(c, v.z, d.z); d.w = fmaf(c, v.w, d.w);
    ((float4*)dst)[i] = d;
}

// ---------------- fused flash attention pass ----------------
// O = softmax(Q Kt^T * scale) @ Vin     (per head, Lq=Lk=2048, hd=dv=64)
// If csum != nullptr (P-floor path):
//   O = (1-1e-6) * softmaxPV + (1e-6/SEQ) * csum[h][:]
// outmode 0: Out[h][l][d] head-split;  outmode 1: Out[l][h*64+d] interleaved
__global__ __launch_bounds__(256) void attn_kernel(
    const float* __restrict__ Qg, const float* __restrict__ Kg,
    const float* __restrict__ Vg, float* __restrict__ Og,
    const float* __restrict__ csum, float scale, int outmode)
{
    extern __shared__ float sm[];
    float* sQ = sm;                 // 64 x 64 (pitch 64)
    float* sK = sm + 4096;          // 64 x 65 (pitch 65, avoids column-read conflicts)
    float* sV = sm + 4096 + 4160;   // 64 x 64 (pitch 64, float4 reads)
    float* sP = sV + 4096;          // 64 x 64 (pitch 64)

    const int h  = blockIdx.y;
    const int q0 = blockIdx.x * 64;
    const float* Qh = Qg + (size_t)h * LHD + (size_t)q0 * HD;
    const float* Kh = Kg + (size_t)h * LHD;
    const float* Vh = Vg + (size_t)h * LHD;

    const int tid = threadIdx.x;
    const int ty = tid >> 4, tx = tid & 15;   // thread owns rows 4ty..+3, cols 4tx..+3

    // load Q tile (contiguous 16KB)
    for (int i = tid; i < 1024; i += 256)
        ((float4*)sQ)[i] = ((const float4*)Qh)[i];

    float m_i[4], l_i[4], O[4][4];
    #pragma unroll
    for (int i = 0; i < 4; i++) {
        m_i[i] = -1e30f; l_i[i] = 0.f;
        #pragma unroll
        for (int j = 0; j < 4; j++) O[i][j] = 0.f;
    }

    for (int kt = 0; kt < SEQ / 64; kt++) {
        __syncthreads();   // protect sK/sV/sP WAR from previous iteration
        const float* Kt = Kh + (size_t)kt * 64 * HD;
        for (int idx = tid; idx < 1024; idx += 256) {
            int row = idx >> 4, q = idx & 15;
            float4 k4 = ((const float4*)Kt)[idx];
            float* d = sK + row * 65 + q * 4;
            d[0] = k4.x; d[1] = k4.y; d[2] = k4.z; d[3] = k4.w;
        }
        const float* Vt = Vh + (size_t)kt * 64 * HD;
        for (int i = tid; i < 1024; i += 256)
            ((float4*)sV)[i] = ((const float4*)Vt)[i];
        __syncthreads();

        // ---- S = Q K^T ----
        float s[4][4];
        #pragma unroll
        for (int i = 0; i < 4; i++)
            #pragma unroll
            for (int j = 0; j < 4; j++) s[i][j] = 0.f;

        #pragma unroll 8
        for (int d = 0; d < 64; d++) {
            float qf[4], kf[4];
            #pragma unroll
            for (int i = 0; i < 4; i++) qf[i] = sQ[(4*ty + i) * 64 + d];
            #pragma unroll
            for (int j = 0; j < 4; j++) kf[j] = sK[(4*tx + j) * 65 + d];
            #pragma unroll
            for (int i = 0; i < 4; i++)
                #pragma unroll
                for (int j = 0; j < 4; j++) s[i][j] = fmaf(qf[i], kf[j], s[i][j]);
        }
        #pragma unroll
        for (int i = 0; i < 4; i++)
            #pragma unroll
            for (int j = 0; j < 4; j++) s[i][j] *= scale;

        // ---- online softmax ----
        float mt[4], mnew[4], corr[4], rs[4];
        #pragma unroll
        for (int i = 0; i < 4; i++) {
            mt[i] = fmaxf(fmaxf(s[i][0], s[i][1]), fmaxf(s[i][2], s[i][3]));
            #pragma unroll
            for (int o = 8; o; o >>= 1)
                mt[i] = fmaxf(mt[i], __shfl_xor_sync(0xffffffffu, mt[i], o));
            mnew[i] = fmaxf(m_i[i], mt[i]);
            corr[i] = __expf(m_i[i] - mnew[i]);
        }
        #pragma unroll
        for (int i = 0; i < 4; i++) {
            float p[4];
            #pragma unroll
            for (int j = 0; j < 4; j++) p[j] = __expf(s[i][j] - mnew[i]);
            rs[i] = p[0] + p[1] + p[2] + p[3];
            *(float4*)(sP + (4*ty + i) * 64 + 4*tx) = *(float4*)p;
            #pragma unroll
            for (int o = 8; o; o >>= 1)
                rs[i] += __shfl_xor_sync(0xffffffffu, rs[i], o);
            l_i[i] = l_i[i] * corr[i] + rs[i];
            m_i[i] = mnew[i];
            #pragma unroll
            for (int j = 0; j < 4; j++) O[i][j] *= corr[i];
        }
        __syncthreads();

        // ---- O += P @ V ----
        #pragma unroll 8
        for (int k = 0; k < 64; k++) {
            float4 v4 = *(float4*)(sV + k * 64 + 4 * tx);
            float pf[4];
            #pragma unroll
            for (int i = 0; i < 4; i++) pf[i] = sP[(4*ty + i) * 64 + k];
            #pragma unroll
            for (int i = 0; i < 4; i++) {
                O[i][0] = fmaf(pf[i], v4.x, O[i][0]);
                O[i][1] = fmaf(pf[i], v4.y, O[i][1]);
                O[i][2] = fmaf(pf[i], v4.z, O[i][2]);
                O[i][3] = fmaf(pf[i], v4.w, O[i][3]);
            }
        }
    }

    // ---- epilogue ----
    const float om = 1.f - 1e-6f;
    const float fl = 1e-6f / (float)SEQ;
    #pragma unroll
    for (int i = 0; i < 4; i++) {
        float inv = 1.f / l_i[i];
        float o[4];
        #pragma unroll
        for (int j = 0; j < 4; j++) o[j] = O[i][j] * inv;
        if (csum) {
            #pragma unroll
            for (int j = 0; j < 4; j++)
                o[j] = o[j] * om + fl * csum[h * HD + 4*tx + j];
        }
        int row = q0 + 4*ty + i;
        float* dst = (outmode == 0)
            ? Og + ((size_t)h * SEQ + row) * HD + 4*tx
            : Og + (size_t)row * EMB + h * HD + 4*tx;
        *(float4*)dst = *(float4*)o;
    }
}

// ---------------- launch ----------------
extern "C" void kernel_launch(void* const* d_in, const int* in_sizes, int n_in,
                              void* d_out, int out_size)
{
    const float* X  = (const float*)d_in[0];
    const float* Wq = (const float*)d_in[1];
    const float* bq = (const float*)d_in[2];
    const float* Wk = (const float*)d_in[3];
    const float* bk = (const float*)d_in[4];
    const float* Wv = (const float*)d_in[5];
    const float* bv = (const float*)d_in[6];
    const float* Wo = (const float*)d_in[7];
    const float* bo = (const float*)d_in[8];

    float *Qd, *Kd, *Vd, *Knd, *ud, *u2d, *Vpd, *attnd, *csd;
    cudaGetSymbolAddress((void**)&Qd,   g_Q);
    cudaGetSymbolAddress((void**)&Kd,   g_K);
    cudaGetSymbolAddress((void**)&Vd,   g_V);
    cudaGetSymbolAddress((void**)&Knd,  g_Kn);
    cudaGetSymbolAddress((void**)&ud,   g_u);
    cudaGetSymbolAddress((void**)&u2d,  g_u2);
    cudaGetSymbolAddress((void**)&Vpd,  g_Vp);
    cudaGetSymbolAddress((void**)&attnd,g_attn);
    cudaGetSymbolAddress((void**)&csd,  g_csum);

    const size_t ATTN_SMEM = (size_t)(4096 + 4160 + 4096 + 4096) * sizeof(float); // 65792
    cudaFuncSetAttribute(attn_kernel, cudaFuncAttributeMaxDynamicSharedMemorySize,
                         (int)ATTN_SMEM);

    // 1) fused Q/K/V projections (head-split outputs)
    dim3 gqkv(EMB / 128, SEQ / 128, 3);
    gemm_kernel<0><<<gqkv, 256>>>(X, Wq, bq, Qd, Wk, bk, Kd, Wv, bv, Vd,
                                  SEQ, EMB, EMB);

    // 2) Kn = normalize(K)
    knorm_kernel<<<(NHEADS * SEQ) / 8, 256>>>(Kd, Knd);

    // 3) diffusion as 4 attention passes over P = eps-floored softmax(Kn Kn^T / 8)
    //    V' = 0.98*(V + a*u1 + a^2*u2 + a^3*u3) + a^4*u4
    dim3 gattn(SEQ / 64, NHEADS);
    const int NB = (TOT / 4) / 256;   // float4 elementwise grid
    const float scl = 0.125f;         // 1/sqrt(64), TEMP=1

    scale_kernel<<<NB, 256>>>(Vpd, Vd, 0.98f);

    colsum_kernel<<<NHEADS, 256>>>(Vd, csd);
    attn_kernel<<<gattn, 256, ATTN_SMEM>>>(Knd, Knd, Vd, ud, csd, scl, 0);
    axpy_kernel<<<NB, 256>>>(Vpd, ud, 0.98f * 0.02f);

    colsum_kernel<<<NHEADS, 256>>>(ud, csd);
    attn_kernel<<<gattn, 256, ATTN_SMEM>>>(Knd, Knd, ud, u2d, csd, scl, 0);
    axpy_kernel<<<NB, 256>>>(Vpd, u2d, 0.98f * 0.0004f);

    colsum_kernel<<<NHEADS, 256>>>(u2d, csd);
    attn_kernel<<<gattn, 256, ATTN_SMEM>>>(Knd, Knd, u2d, ud, csd, scl, 0);
    axpy_kernel<<<NB, 256>>>(Vpd, ud, 0.98f * 8e-6f);

    colsum_kernel<<<NHEADS, 256>>>(ud, csd);
    attn_kernel<<<gattn, 256, ATTN_SMEM>>>(Knd, Knd, ud, u2d, csd, scl, 0);
    axpy_kernel<<<NB, 256>>>(Vpd, u2d, 1.6e-7f);

    // 4) final attention with modified values: out = softmax(QK^T/8) @ V'
    attn_kernel<<<gattn, 256, ATTN_SMEM>>>(Qd, Kd, Vpd, attnd, nullptr, scl, 1);

    // 5) output projection -> d_out (row-major L x EMB)
    dim3 go(EMB / 128, SEQ / 128, 1);
    gemm_kernel<1><<<go, 256>>>(attnd, Wo, bo, (float*)d_out,
                                Wo, bo, (float*)d_out,
                                Wo, bo, (float*)d_out,
                                SEQ, EMB, EMB);
}

// round 3
// speedup vs baseline: 1.8723x; 1.8723x over previous
#include <cuda_runtime.h>
#include <cuda_bf16.h>
#include <mma.h>
#include <math.h>
#include <stdint.h>

using namespace nvcuda;

#define NHEADS 16
#define SEQ    2048
#define HD     64
#define EMB    1024
#define LHD    (SEQ*HD)
#define TOT    (NHEADS*SEQ*HD)

// ---------------- scratch (device globals; no allocations) ----------------
__device__ float g_Q[TOT];
__device__ float g_K[TOT];
__device__ float g_V[TOT];
__device__ float g_Kn[TOT];
__device__ float g_u[TOT];
__device__ float g_u2[TOT];
__device__ float g_Vp[TOT];
__device__ float g_attn[SEQ*EMB];

// ---------------- bf16 hi/lo split helpers ----------------
__device__ __forceinline__ uint32_t pack2(__nv_bfloat16 a, __nv_bfloat16 b) {
    uint16_t x = *(uint16_t*)&a, y = *(uint16_t*)&b;
    return (uint32_t)x | ((uint32_t)y << 16);
}
__device__ __forceinline__ void split_pack(float a, float b, uint32_t& hi, uint32_t& lo) {
    __nv_bfloat16 ha = __float2bfloat16(a), hb = __float2bfloat16(b);
    float la = a - __bfloat162float(ha), lb = b - __bfloat162float(hb);
    hi = pack2(ha, hb);
    lo = pack2(__float2bfloat16(la), __float2bfloat16(lb));
}

// ============================================================================
// WMMA flash attention pass
// O = softmax(Q K^T * scale) @ V * om     (per head; Lq tile = 128, 32 K-tiles)
// SPLIT=1: bf16 hi/lo 3-term compensation on both GEMMs (final pass).
// SPLIT=0: plain bf16 (alpha-suppressed diffusion passes).
// grid (SEQ/128, NHEADS), 256 threads (8 warps; warp w owns q-rows 16w..16w+15)
// ============================================================================
// smem byte offsets (bf16 tiles padded to ld=72, fp32 scores ld=68)
#define O_QH 0          // 128x72 bf16  (18432)
#define O_QL 18432
#define O_KH 36864      // 64x72 bf16   (9216)
#define O_KL 46080
#define O_VH 55296
#define O_VL 64512
#define O_PH 73728      // 128x72 bf16
#define O_PL 92160
#define O_S  110592     // 128x68 fp32  (34816)
#define O_RS 145408     // 128 fp32 row inv-sums
#define ATTN_SMEM 145920

template<int SPLIT>
__global__ __launch_bounds__(256) void attn_mma_kernel(
    const float* __restrict__ Qg, const float* __restrict__ Kg,
    const float* __restrict__ Vg, float* __restrict__ Og,
    float scale, float om, int outmode)
{
    extern __shared__ char sm[];
    __nv_bfloat16* Qh = (__nv_bfloat16*)(sm + O_QH);
    __nv_bfloat16* Ql = (__nv_bfloat16*)(sm + O_QL);
    __nv_bfloat16* Kh = (__nv_bfloat16*)(sm + O_KH);
    __nv_bfloat16* Kl = (__nv_bfloat16*)(sm + O_KL);
    __nv_bfloat16* Vh = (__nv_bfloat16*)(sm + O_VH);
    __nv_bfloat16* Vl = (__nv_bfloat16*)(sm + O_VL);
    __nv_bfloat16* Ph = (__nv_bfloat16*)(sm + O_PH);
    __nv_bfloat16* Pl = (__nv_bfloat16*)(sm + O_PL);
    float* Ssm  = (float*)(sm + O_S);
    float* rsum = (float*)(sm + O_RS);

    const int tid = threadIdx.x;
    const int w = tid >> 5;
    const int h = blockIdx.y;
    const int q0 = blockIdx.x * 128;

    // ---- load Q tile 128x64 fp32 -> bf16 hi/lo ----
    const float* Qp = Qg + ((size_t)h * SEQ + q0) * HD;
    for (int i = tid; i < 2048; i += 256) {
        int row = i >> 4, cg = i & 15;
        float4 v = ((const float4*)Qp)[i];
        uint32_t h0, l0, h1, l1;
        split_pack(v.x, v.y, h0, l0);
        split_pack(v.z, v.w, h1, l1);
        int e = row * 72 + cg * 4;
        *(uint2*)(Qh + e) = make_uint2(h0, h1);
        if (SPLIT) *(uint2*)(Ql + e) = make_uint2(l0, l1);
    }
    __syncthreads();

    // persistent Q fragments (row-major, m-tile = warp id)
    wmma::fragment<wmma::matrix_a, 16, 16, 16, __nv_bfloat16, wmma::row_major> aQh[4], aQl[4];
    #pragma unroll
    for (int ks = 0; ks < 4; ks++) {
        wmma::load_matrix_sync(aQh[ks], Qh + w * 16 * 72 + ks * 16, 72);
        if (SPLIT) wmma::load_matrix_sync(aQl[ks], Ql + w * 16 * 72 + ks * 16, 72);
    }

    wmma::fragment<wmma::accumulator, 16, 16, 16, float> Ofr[4];
    #pragma unroll
    for (int j = 0; j < 4; j++) wmma::fill_fragment(Ofr[j], 0.f);

    float lsum = 0.f;
    const int srow = tid >> 1, scol = (tid & 1) * 32;
    const float* Kp = Kg + (size_t)h * LHD;
    const float* Vp = Vg + (size_t)h * LHD;

    for (int kt = 0; kt < 32; kt++) {
        __syncthreads();   // previous iter PV reads done before overwriting K/V
        // ---- stage K,V 64x64 tiles -> bf16 (hi/lo) ----
        const float4* K4 = (const float4*)(Kp + (size_t)kt * 64 * HD);
        const float4* V4 = (const float4*)(Vp + (size_t)kt * 64 * HD);
        for (int i = tid; i < 1024; i += 256) {
            int row = i >> 4, cg = i & 15;
            int e = row * 72 + cg * 4;
            float4 v = K4[i];
            uint32_t h0, l0, h1, l1;
            split_pack(v.x, v.y, h0, l0);
            split_pack(v.z, v.w, h1, l1);
            *(uint2*)(Kh + e) = make_uint2(h0, h1);
            if (SPLIT) *(uint2*)(Kl + e) = make_uint2(l0, l1);
            v = V4[i];
            split_pack(v.x, v.y, h0, l0);
            split_pack(v.z, v.w, h1, l1);
            *(uint2*)(Vh + e) = make_uint2(h0, h1);
            if (SPLIT) *(uint2*)(Vl + e) = make_uint2(l0, l1);
        }
        __syncthreads();

        // ---- S = (Q K^T) * scale ----
        #pragma unroll
        for (int nt = 0; nt < 4; nt++) {
            wmma::fragment<wmma::accumulator, 16, 16, 16, float> s;
            wmma::fill_fragment(s, 0.f);
            #pragma unroll
            for (int ks = 0; ks < 4; ks++) {
                wmma::fragment<wmma::matrix_b, 16, 16, 16, __nv_bfloat16, wmma::col_major> bh;
                wmma::load_matrix_sync(bh, Kh + nt * 16 * 72 + ks * 16, 72);
                wmma::mma_sync(s, aQh[ks], bh, s);
                if (SPLIT) {
                    wmma::fragment<wmma::matrix_b, 16, 16, 16, __nv_bfloat16, wmma::col_major> bl;
                    wmma::load_matrix_sync(bl, Kl + nt * 16 * 72 + ks * 16, 72);
                    wmma::mma_sync(s, aQh[ks], bl, s);
                    wmma::mma_sync(s, aQl[ks], bh, s);
                }
            }
            #pragma unroll
            for (int e = 0; e < s.num_elements; e++) s.x[e] *= scale;
            wmma::store_matrix_sync(Ssm + w * 16 * 68 + nt * 16, s, 68, wmma::mem_row_major);
        }
        __syncthreads();

        // ---- p = exp(s); row sums; stage P (hi/lo) ----
        {
            const float* sp = Ssm + srow * 68 + scol;
            __nv_bfloat16* php = Ph + srow * 72 + scol;
            __nv_bfloat16* plp = Pl + srow * 72 + scol;
            #pragma unroll
            for (int j = 0; j < 32; j += 2) {
                float p0 = __expf(sp[j]), p1 = __expf(sp[j + 1]);
                lsum += p0 + p1;
                __nv_bfloat16 b0 = __float2bfloat16(p0), b1 = __float2bfloat16(p1);
                *(uint32_t*)(php + j) = pack2(b0, b1);
                if (SPLIT)
                    *(uint32_t*)(plp + j) =
                        pack2(__float2bfloat16(p0 - __bfloat162float(b0)),
                              __float2bfloat16(p1 - __bfloat162float(b1)));
            }
        }
        __syncthreads();

        // ---- O += P @ V ----
        wmma::fragment<wmma::matrix_a, 16, 16, 16, __nv_bfloat16, wmma::row_major> pH[4], pL[4];
        #pragma unroll
        for (int ks = 0; ks < 4; ks++) {
            wmma::load_matrix_sync(pH[ks], Ph + w * 16 * 72 + ks * 16, 72);
            if (SPLIT) wmma::load_matrix_sync(pL[ks], Pl + w * 16 * 72 + ks * 16, 72);
        }
        #pragma unroll
        for (int nt = 0; nt < 4; nt++) {
            #pragma unroll
            for (int ks = 0; ks < 4; ks++) {
                wmma::fragment<wmma::matrix_b, 16, 16, 16, __nv_bfloat16, wmma::row_major> bh;
                wmma::load_matrix_sync(bh, Vh + ks * 16 * 72 + nt * 16, 72);
                wmma::mma_sync(Ofr[nt], pH[ks], bh, Ofr[nt]);
                if (SPLIT) {
                    wmma::fragment<wmma::matrix_b, 16, 16, 16, __nv_bfloat16, wmma::row_major> bl;
                    wmma::load_matrix_sync(bl, Vl + ks * 16 * 72 + nt * 16, 72);
                    wmma::mma_sync(Ofr[nt], pH[ks], bl, Ofr[nt]);
                    wmma::mma_sync(Ofr[nt], pL[ks], bh, Ofr[nt]);
                }
            }
        }
    }

    // ---- epilogue: normalize by row sums, write ----
    float tot = lsum + __shfl_xor_sync(0xffffffffu, lsum, 1);
    if (!(tid & 1)) rsum[srow] = om / tot;
    __syncthreads();
    #pragma unroll
    for (int nt = 0; nt < 4; nt++)
        wmma::store_matrix_sync(Ssm + w * 16 * 68 + nt * 16, Ofr[nt], 68, wmma::mem_row_major);
    __syncthreads();
    {
        float inv = rsum[srow];
        int row = q0 + srow;
        float* dst = outmode ? Og + (size_t)row * EMB + h * HD + scol
                             : Og + ((size_t)h * SEQ + row) * HD + scol;
        const float* sp = Ssm + srow * 68 + scol;
        #pragma unroll
        for (int j = 0; j < 32; j += 4) {
            float4 o;
            o.x = sp[j] * inv; o.y = sp[j + 1] * inv;
            o.z = sp[j + 2] * inv; o.w = sp[j + 3] * inv;
            *(float4*)(dst + j) = o;
        }
    }
}

// ============================================================================
// WMMA split-3 GEMM: C = A(MxK) @ B(KxN) + bias
// MODE 0: head-split output  C[h][m][d],  MODE 1: row-major C[m][n]
// blockIdx.z selects (B,bias,C) triple (fused QKV).
// Tile 128x128, k-step 32, 256 threads (8 warps: mw=w&3 owns 2 m-tiles,
// nw=w>>2 owns 4 n-tiles).
// ============================================================================
template<int MODE>
__global__ __launch_bounds__(256) void gemm_mma_kernel(
    const float* __restrict__ A,
    const float* __restrict__ B0, const float* __restrict__ bias0, float* __restrict__ C0,
    const float* __restrict__ B1, const float* __restrict__ bias1, float* __restrict__ C1,
    const float* __restrict__ B2, const float* __restrict__ bias2, float* __restrict__ C2,
    int M, int N, int K)
{
    const float* B; const float* bias; float* C;
    if (blockIdx.z == 0)      { B = B0; bias = bias0; C = C0; }
    else if (blockIdx.z == 1) { B = B1; bias = bias1; C = C1; }
    else                      { B = B2; bias = bias2; C = C2; }

    __shared__ __align__(16) char smb[37888];
    __nv_bfloat16* Ah = (__nv_bfloat16*)smb;       // 128x40 bf16
    __nv_bfloat16* Al = Ah + 5120;
    __nv_bfloat16* Bh = Al + 5120;                 // 32x136 bf16
    __nv_bfloat16* Bl = Bh + 4352;
    float* scratch = (float*)smb;                  // 128x68 fp32 (epilogue alias)

    const int tid = threadIdx.x;
    const int w = tid >> 5;
    const int mw = w & 3, nw = w >> 2;
    const int m0 = blockIdx.y * 128, n0 = blockIdx.x * 128;

    wmma::fragment<wmma::accumulator, 16, 16, 16, float> acc[2][4];
    #pragma unroll
    for (int mi = 0; mi < 2; mi++)
        #pragma unroll
        for (int j = 0; j < 4; j++) wmma::fill_fragment(acc[mi][j], 0.f);

    for (int k0 = 0; k0 < K; k0 += 32) {
        __syncthreads();
        for (int i = tid; i < 1024; i += 256) {         // A tile 128x32
            int row = i >> 3, cg = i & 7;
            float4 v = *(const float4*)(A + (size_t)(m0 + row) * K + k0 + cg * 4);
            uint32_t h0, l0, h1, l1;
            split_pack(v.x, v.y, h0, l0);
            split_pack(v.z, v.w, h1, l1);
            int e = row * 40 + cg * 4;
            *(uint2*)(Ah + e) = make_uint2(h0, h1);
            *(uint2*)(Al + e) = make_uint2(l0, l1);
        }
        for (int i = tid; i < 1024; i += 256) {         // B tile 32x128
            int row = i >> 5, cg = i & 31;
            float4 v = *(const float4*)(B + (size_t)(k0 + row) * N + n0 + cg * 4);
            uint32_t h0, l0, h1, l1;
            split_pack(v.x, v.y, h0, l0);
            split_pack(v.z, v.w, h1, l1);
            int e = row * 136 + cg * 4;
            *(uint2*)(Bh + e) = make_uint2(h0, h1);
            *(uint2*)(Bl + e) = make_uint2(l0, l1);
        }
        __syncthreads();

        #pragma unroll
        for (int ks = 0; ks < 2; ks++) {
            wmma::fragment<wmma::matrix_a, 16, 16, 16, __nv_bfloat16, wmma::row_major> ah[2], al[2];
            #pragma unroll
            for (int mi = 0; mi < 2; mi++) {
                wmma::load_matrix_sync(ah[mi], Ah + (mw * 32 + mi * 16) * 40 + ks * 16, 40);
                wmma::load_matrix_sync(al[mi], Al + (mw * 32 + mi * 16) * 40 + ks * 16, 40);
            }
            #pragma unroll
            for (int j = 0; j < 4; j++) {
                wmma::fragment<wmma::matrix_b, 16, 16, 16, __nv_bfloat16, wmma::row_major> bh, bl;
                wmma::load_matrix_sync(bh, Bh + ks * 16 * 136 + nw * 64 + j * 16, 136);
                wmma::load_matrix_sync(bl, Bl + ks * 16 * 136 + nw * 64 + j * 16, 136);
                #pragma unroll
                for (int mi = 0; mi < 2; mi++) {
                    wmma::mma_sync(acc[mi][j], ah[mi], bh, acc[mi][j]);
                    wmma::mma_sync(acc[mi][j], ah[mi], bl, acc[mi][j]);
                    wmma::mma_sync(acc[mi][j], al[mi], bh, acc[mi][j]);
                }
            }
        }
    }

    // ---- epilogue: two 64-col phases through fp32 scratch ----
    const int erow = tid >> 1, elc = (tid & 1) * 32;
    #pragma unroll
    for (int phse = 0; phse < 2; phse++) {
        __syncthreads();
        if (nw == phse) {
            #pragma unroll
            for (int mi = 0; mi < 2; mi++)
                #pragma unroll
                for (int j = 0; j < 4; j++)
                    wmma::store_matrix_sync(scratch + (mw * 32 + mi * 16) * 68 + j * 16,
                                            acc[mi][j], 68, wmma::mem_row_major);
        }
        __syncthreads();
        int gc0 = n0 + phse * 64 + elc;
        int m = m0 + erow;
        const float* sp = scratch + erow * 68 + elc;
        float* dst;
        if (MODE == 0) {
            int hh = gc0 >> 6, d = gc0 & 63;
            dst = C + ((size_t)hh * SEQ + m) * HD + d;
        } else {
            dst = C + (size_t)m * N + gc0;
        }
        #pragma unroll
        for (int j = 0; j < 32; j += 4) {
            float4 o;
            o.x = sp[j]     + bias[gc0 + j];
            o.y = sp[j + 1] + bias[gc0 + j + 1];
            o.z = sp[j + 2] + bias[gc0 + j + 2];
            o.w = sp[j + 3] + bias[gc0 + j + 3];
            *(float4*)(dst + j) = o;
        }
    }
}

// ---------------- K row-normalize ----------------
__global__ __launch_bounds__(256) void knorm_kernel(const float* __restrict__ K,
                                                    float* __restrict__ Kn)
{
    int row  = blockIdx.x * 8 + (threadIdx.x >> 5);
    int lane = threadIdx.x & 31;
    const float* kr = K + (size_t)row * HD;
    float v0 = kr[lane], v1 = kr[lane + 32];
    float ss = v0 * v0 + v1 * v1;
    #pragma unroll
    for (int o = 16; o; o >>= 1) ss += __shfl_xor_sync(0xffffffffu, ss, o);
    float inv = 1.f / fmaxf(sqrtf(ss), 1e-6f);
    Kn[(size_t)row * HD + lane]      = v0 * inv;
    Kn[(size_t)row * HD + lane + 32] = v1 * inv;
}

// ---------------- elementwise ----------------
__global__ __launch_bounds__(256) void scale_kernel(float* __restrict__ dst,
                                                    const float* __restrict__ src, float c)
{
    int i = blockIdx.x * 256 + threadIdx.x;
    float4 v = ((const float4*)src)[i];
    v.x *= c; v.y *= c; v.z *= c; v.w *= c;
    ((float4*)dst)[i] = v;
}
__global__ __launch_bounds__(256) void axpy_kernel(float* __restrict__ dst,
                                                   const float* __restrict__ src, float c)
{
    int i = blockIdx.x * 256 + threadIdx.x;
    float4 v = ((const float4*)src)[i];
    float4 d = ((float4*)dst)[i];
    d.x = fmaf(c, v.x, d.x); d.y = fmaf(c, v.y, d.y);
    d.z = fmaf(c, v.z, d.z); d.w = fmaf(c, v.w, d.w);
    ((float4*)dst)[i] = d;
}

// ---------------- launch ----------------
extern "C" void kernel_launch(void* const* d_in, const int* in_sizes, int n_in,
                              void* d_out, int out_size)
{
    const float* X  = (const float*)d_in[0];
    const float* Wq = (const float*)d_in[1];
    const float* bq = (const float*)d_in[2];
    const float* Wk = (const float*)d_in[3];
    const float* bk = (const float*)d_in[4];
    const float* Wv = (const float*)d_in[5];
    const float* bv = (const float*)d_in[6];
    const float* Wo = (const float*)d_in[7];
    const float* bo = (const float*)d_in[8];

    float *Qd, *Kd, *Vd, *Knd, *ud, *u2d, *Vpd, *attnd;
    cudaGetSymbolAddress((void**)&Qd,    g_Q);
    cudaGetSymbolAddress((void**)&Kd,    g_K);
    cudaGetSymbolAddress((void**)&Vd,    g_V);
    cudaGetSymbolAddress((void**)&Knd,   g_Kn);
    cudaGetSymbolAddress((void**)&ud,    g_u);
    cudaGetSymbolAddress((void**)&u2d,   g_u2);
    cudaGetSymbolAddress((void**)&Vpd,   g_Vp);
    cudaGetSymbolAddress((void**)&attnd, g_attn);

    cudaFuncSetAttribute(attn_mma_kernel<0>,
                         cudaFuncAttributeMaxDynamicSharedMemorySize, ATTN_SMEM);
    cudaFuncSetAttribute(attn_mma_kernel<1>,
                         cudaFuncAttributeMaxDynamicSharedMemorySize, ATTN_SMEM);

    const float scl = 0.125f;           // 1/sqrt(64), TEMP=1
    const float om  = 1.f - 1e-6f;      // P floor multiplier (additive part negligible)
    const int NB = (TOT / 4) / 256;
    dim3 gattn(SEQ / 128, NHEADS);

    // 1) fused Q/K/V projections (head-split outputs)
    dim3 gqkv(EMB / 128, SEQ / 128, 3);
    gemm_mma_kernel<0><<<gqkv, 256>>>(X, Wq, bq, Qd, Wk, bk, Kd, Wv, bv, Vd,
                                      SEQ, EMB, EMB);

    // 2) Kn = normalize(K)
    knorm_kernel<<<(NHEADS * SEQ) / 8, 256>>>(Kd, Knd);

    // 3) diffusion: V' = 0.98*(V + a*u1 + a^2*u2 + a^3*u3)   [a^4 u4 term ~1.6e-7: dropped]
    scale_kernel<<<NB, 256>>>(Vpd, Vd, 0.98f);

    attn_mma_kernel<0><<<gattn, 256, ATTN_SMEM>>>(Knd, Knd, Vd, ud, scl, om, 0);
    axpy_kernel<<<NB, 256>>>(Vpd, ud, 0.98f * 0.02f);

    attn_mma_kernel<0><<<gattn, 256, ATTN_SMEM>>>(Knd, Knd, ud, u2d, scl, om, 0);
    axpy_kernel<<<NB, 256>>>(Vpd, u2d, 0.98f * 0.0004f);

    attn_mma_kernel<0><<<gattn, 256, ATTN_SMEM>>>(Knd, Knd, u2d, ud, scl, om, 0);
    axpy_kernel<<<NB, 256>>>(Vpd, ud, 0.98f * 8e-6f);

    // 4) final attention: out = softmax(QK^T/8) @ V'  (interleaved layout, split-3)
    attn_mma_kernel<1><<<gattn, 256, ATTN_SMEM>>>(Qd, Kd, Vpd, attnd, scl, 1.0f, 1);

    // 5) output projection -> d_out
    dim3 go(EMB / 128, SEQ / 128, 1);
    gemm_mma_kernel<1><<<go, 256>>>(attnd, Wo, bo, (float*)d_out,
                                    Wo, bo, (float*)d_out,
                                    Wo, bo, (float*)d_out,
                                    SEQ, EMB, EMB);
}

// round 4
// speedup vs baseline: 2.4217x; 1.2934x over previous
#include <cuda_runtime.h>
#include <cuda_bf16.h>
#include <mma.h>
#include <math.h>
#include <stdint.h>

using namespace nvcuda;

#define NHEADS 16
#define SEQ    2048
#define HD     64
#define EMB    1024
#define LHD    (SEQ*HD)
#define TOT    (NHEADS*SEQ*HD)

// ---------------- scratch (device globals; no allocations) ----------------
__device__ float g_Q[TOT];
__device__ float g_K[TOT];
__device__ float g_V[TOT];
__device__ float g_Kn[TOT];
__device__ float g_u[TOT];
__device__ float g_u2[TOT];
__device__ float g_Vp[TOT];
__device__ float g_attn[SEQ*EMB];
// bf16 operand buffers
__device__ __nv_bfloat16 g_bKnA[TOT];   // Kn * scale (A side)
__device__ __nv_bfloat16 g_bKnB[TOT];   // Kn (B side)
__device__ __nv_bfloat16 g_bX[TOT];     // per-pass V-side operand
__device__ __nv_bfloat16 g_bQh[TOT], g_bQl[TOT];
__device__ __nv_bfloat16 g_bKh[TOT], g_bKl[TOT];
__device__ __nv_bfloat16 g_bVh[TOT], g_bVl[TOT];

// ---------------- bf16 helpers ----------------
__device__ __forceinline__ uint32_t pack2(__nv_bfloat16 a, __nv_bfloat16 b) {
    uint16_t x = *(uint16_t*)&a, y = *(uint16_t*)&b;
    return (uint32_t)x | ((uint32_t)y << 16);
}
__device__ __forceinline__ void split_pack(float a, float b, uint32_t& hi, uint32_t& lo) {
    __nv_bfloat16 ha = __float2bfloat16(a), hb = __float2bfloat16(b);
    float la = a - __bfloat162float(ha), lb = b - __bfloat162float(hb);
    hi = pack2(ha, hb);
    lo = pack2(__float2bfloat16(la), __float2bfloat16(lb));
}

// ---------------- fp32 -> bf16 (hi[, lo]) with scale ----------------
template<int HASLO>
__global__ __launch_bounds__(256) void cvt_kernel(const float* __restrict__ in,
                                                  __nv_bfloat16* __restrict__ hi,
                                                  __nv_bfloat16* __restrict__ lo,
                                                  float scale)
{
    int i = blockIdx.x * 256 + threadIdx.x;      // float4 index
    float4 v = ((const float4*)in)[i];
    v.x *= scale; v.y *= scale; v.z *= scale; v.w *= scale;
    uint32_t h0, l0, h1, l1;
    split_pack(v.x, v.y, h0, l0);
    split_pack(v.z, v.w, h1, l1);
    ((uint2*)hi)[i] = make_uint2(h0, h1);
    if (HASLO) ((uint2*)lo)[i] = make_uint2(l0, l1);
}

// ============================================================================
// WMMA flash attention pass (bf16 global operands, pre-converted)
// O = softmax(A_scaled @ K^T) @ V      (scale pre-folded into A)
// SPLIT=1: hi/lo 3-term compensation on both GEMMs.
// grid (SEQ/64, NHEADS), 128 threads (4 warps; warp w owns q-rows 16w..16w+15)
// ============================================================================
#define A_QH 0              // 64x72 bf16 (9216B)
#define A_KH 9216
#define A_VH 18432
#define A_PH 27648
#define A_S  36864          // 64x68 fp32 (17408B)
#define A_RS 54272          // 64 fp32
#define SM0  54528
#define A_QL 54528
#define A_KL 63744
#define A_VL 72960
#define A_PL 82176
#define SM1  91392

template<int SPLIT>
__global__ __launch_bounds__(128) void attn_kernel(
    const __nv_bfloat16* __restrict__ Ah, const __nv_bfloat16* __restrict__ Al,
    const __nv_bfloat16* __restrict__ Kg, const __nv_bfloat16* __restrict__ Kl,
    const __nv_bfloat16* __restrict__ Vg, const __nv_bfloat16* __restrict__ Vl,
    float* __restrict__ Og, int outmode)
{
    extern __shared__ char sm[];
    __nv_bfloat16* sQh = (__nv_bfloat16*)(sm + A_QH);
    __nv_bfloat16* sKh = (__nv_bfloat16*)(sm + A_KH);
    __nv_bfloat16* sVh = (__nv_bfloat16*)(sm + A_VH);
    __nv_bfloat16* sPh = (__nv_bfloat16*)(sm + A_PH);
    __nv_bfloat16* sQl = (__nv_bfloat16*)(sm + A_QL);
    __nv_bfloat16* sKl = (__nv_bfloat16*)(sm + A_KL);
    __nv_bfloat16* sVl = (__nv_bfloat16*)(sm + A_VL);
    __nv_bfloat16* sPl = (__nv_bfloat16*)(sm + A_PL);
    float* Ssm  = (float*)(sm + A_S);
    float* rsum = (float*)(sm + A_RS);

    const int tid = threadIdx.x;
    const int w = tid >> 5;
    const int h = blockIdx.y;
    const int q0 = blockIdx.x * 64;

    // ---- stage Q (pure copies; 512 uint4 = 64 rows x 8) ----
    {
        const uint4* Qp = (const uint4*)(Ah + ((size_t)h * SEQ + q0) * HD);
        const uint4* Qpl = SPLIT ? (const uint4*)(Al + ((size_t)h * SEQ + q0) * HD) : nullptr;
        for (int i = tid; i < 512; i += 128) {
            int row = i >> 3, cg = i & 7;
            *(uint4*)(sQh + row * 72 + cg * 8) = Qp[i];
            if (SPLIT) *(uint4*)(sQl + row * 72 + cg * 8) = Qpl[i];
        }
    }
    __syncthreads();

    wmma::fragment<wmma::matrix_a, 16, 16, 16, __nv_bfloat16, wmma::row_major> aQh[4], aQl[4];
    #pragma unroll
    for (int ks = 0; ks < 4; ks++) {
        wmma::load_matrix_sync(aQh[ks], sQh + w * 16 * 72 + ks * 16, 72);
        if (SPLIT) wmma::load_matrix_sync(aQl[ks], sQl + w * 16 * 72 + ks * 16, 72);
    }

    wmma::fragment<wmma::accumulator, 16, 16, 16, float> Ofr[4];
    #pragma unroll
    for (int j = 0; j < 4; j++) wmma::fill_fragment(Ofr[j], 0.f);

    float lsum = 0.f;
    const int srow = tid >> 1, scol = (tid & 1) * 32;
    const uint4* Kp  = (const uint4*)(Kg + (size_t)h * LHD);
    const uint4* Vp  = (const uint4*)(Vg + (size_t)h * LHD);
    const uint4* Kpl = SPLIT ? (const uint4*)(Kl + (size_t)h * LHD) : nullptr;
    const uint4* Vpl = SPLIT ? (const uint4*)(Vl + (size_t)h * LHD) : nullptr;

    for (int kt = 0; kt < 32; kt++) {
        __syncthreads();   // previous iter PV reads done before overwriting K/V
        // ---- stage K,V 64x64 bf16 tiles (copies) ----
        const int base = kt * 512;
        for (int i = tid; i < 512; i += 128) {
            int row = i >> 3, cg = i & 7;
            int e = row * 72 + cg * 8;
            *(uint4*)(sKh + e) = Kp[base + i];
            *(uint4*)(sVh + e) = Vp[base + i];
            if (SPLIT) {
                *(uint4*)(sKl + e) = Kpl[base + i];
                *(uint4*)(sVl + e) = Vpl[base + i];
            }
        }
        __syncthreads();

        // ---- P = exp(Q K^T)  (scale pre-folded into Q) ----
        #pragma unroll
        for (int nt = 0; nt < 4; nt++) {
            wmma::fragment<wmma::accumulator, 16, 16, 16, float> s;
            wmma::fill_fragment(s, 0.f);
            #pragma unroll
            for (int ks = 0; ks < 4; ks++) {
                wmma::fragment<wmma::matrix_b, 16, 16, 16, __nv_bfloat16, wmma::col_major> bh;
                wmma::load_matrix_sync(bh, sKh + nt * 16 * 72 + ks * 16, 72);
                wmma::mma_sync(s, aQh[ks], bh, s);
                if (SPLIT) {
                    wmma::fragment<wmma::matrix_b, 16, 16, 16, __nv_bfloat16, wmma::col_major> bl;
                    wmma::load_matrix_sync(bl, sKl + nt * 16 * 72 + ks * 16, 72);
                    wmma::mma_sync(s, aQh[ks], bl, s);
                    wmma::mma_sync(s, aQl[ks], bh, s);
                }
            }
            #pragma unroll
            for (int e = 0; e < s.num_elements; e++) s.x[e] = __expf(s.x[e]);
            wmma::store_matrix_sync(Ssm + w * 16 * 68 + nt * 16, s, 68, wmma::mem_row_major);
        }
        __syncthreads();

        // ---- row sums; stage P (hi/lo bf16) ----
        {
            const float* sp = Ssm + srow * 68 + scol;
            __nv_bfloat16* php = sPh + srow * 72 + scol;
            __nv_bfloat16* plp = sPl + srow * 72 + scol;
            #pragma unroll
            for (int j = 0; j < 32; j += 2) {
                float p0 = sp[j], p1 = sp[j + 1];
                lsum += p0 + p1;
                __nv_bfloat16 b0 = __float2bfloat16(p0), b1 = __float2bfloat16(p1);
                *(uint32_t*)(php + j) = pack2(b0, b1);
                if (SPLIT)
                    *(uint32_t*)(plp + j) =
                        pack2(__float2bfloat16(p0 - __bfloat162float(b0)),
                              __float2bfloat16(p1 - __bfloat162float(b1)));
            }
        }
        __syncthreads();

        // ---- O += P @ V ----
        wmma::fragment<wmma::matrix_a, 16, 16, 16, __nv_bfloat16, wmma::row_major> pH[4], pL[4];
        #pragma unroll
        for (int ks = 0; ks < 4; ks++) {
            wmma::load_matrix_sync(pH[ks], sPh + w * 16 * 72 + ks * 16, 72);
            if (SPLIT) wmma::load_matrix_sync(pL[ks], sPl + w * 16 * 72 + ks * 16, 72);
        }
        #pragma unroll
        for (int nt = 0; nt < 4; nt++) {
            #pragma unroll
            for (int ks = 0; ks < 4; ks++) {
                wmma::fragment<wmma::matrix_b, 16, 16, 16, __nv_bfloat16, wmma::row_major> bh;
                wmma::load_matrix_sync(bh, sVh + ks * 16 * 72 + nt * 16, 72);
                wmma::mma_sync(Ofr[nt], pH[ks], bh, Ofr[nt]);
                if (SPLIT) {
                    wmma::fragment<wmma::matrix_b, 16, 16, 16, __nv_bfloat16, wmma::row_major> bl;
                    wmma::load_matrix_sync(bl, sVl + ks * 16 * 72 + nt * 16, 72);
                    wmma::mma_sync(Ofr[nt], pH[ks], bl, Ofr[nt]);
                    wmma::mma_sync(Ofr[nt], pL[ks], bh, Ofr[nt]);
                }
            }
        }
    }

    // ---- epilogue: normalize, write ----
    float tot = lsum + __shfl_xor_sync(0xffffffffu, lsum, 1);
    if (!(tid & 1)) rsum[srow] = 1.f / tot;
    __syncthreads();
    #pragma unroll
    for (int nt = 0; nt < 4; nt++)
        wmma::store_matrix_sync(Ssm + w * 16 * 68 + nt * 16, Ofr[nt], 68, wmma::mem_row_major);
    __syncthreads();
    {
        float inv = rsum[srow];
        int row = q0 + srow;
        float* dst = outmode ? Og + (size_t)row * EMB + h * HD + scol
                             : Og + ((size_t)h * SEQ + row) * HD + scol;
        const float* sp = Ssm + srow * 68 + scol;
        #pragma unroll
        for (int j = 0; j < 32; j += 4) {
            float4 o;
            o.x = sp[j] * inv; o.y = sp[j + 1] * inv;
            o.z = sp[j + 2] * inv; o.w = sp[j + 3] * inv;
            *(float4*)(dst + j) = o;
        }
    }
}

// ============================================================================
// WMMA split-3 GEMM (unchanged from R3)
// ============================================================================
template<int MODE>
__global__ __launch_bounds__(256) void gemm_mma_kernel(
    const float* __restrict__ A,
    const float* __restrict__ B0, const float* __restrict__ bias0, float* __restrict__ C0,
    const float* __restrict__ B1, const float* __restrict__ bias1, float* __restrict__ C1,
    const float* __restrict__ B2, const float* __restrict__ bias2, float* __restrict__ C2,
    int M, int N, int K)
{
    const float* B; const float* bias; float* C;
    if (blockIdx.z == 0)      { B = B0; bias = bias0; C = C0; }
    else if (blockIdx.z == 1) { B = B1; bias = bias1; C = C1; }
    else                      { B = B2; bias = bias2; C = C2; }

    __shared__ __align__(16) char smb[37888];
    __nv_bfloat16* Ah = (__nv_bfloat16*)smb;
    __nv_bfloat16* Al = Ah + 5120;
    __nv_bfloat16* Bh = Al + 5120;
    __nv_bfloat16* Bl = Bh + 4352;
    float* scratch = (float*)smb;

    const int tid = threadIdx.x;
    const int w = tid >> 5;
    const int mw = w & 3, nw = w >> 2;
    const int m0 = blockIdx.y * 128, n0 = blockIdx.x * 128;

    wmma::fragment<wmma::accumulator, 16, 16, 16, float> acc[2][4];
    #pragma unroll
    for (int mi = 0; mi < 2; mi++)
        #pragma unroll
        for (int j = 0; j < 4; j++) wmma::fill_fragment(acc[mi][j], 0.f);

    for (int k0 = 0; k0 < K; k0 += 32) {
        __syncthreads();
        for (int i = tid; i < 1024; i += 256) {
            int row = i >> 3, cg = i & 7;
            float4 v = *(const float4*)(A + (size_t)(m0 + row) * K + k0 + cg * 4);
            uint32_t h0, l0, h1, l1;
            split_pack(v.x, v.y, h0, l0);
            split_pack(v.z, v.w, h1, l1);
            int e = row * 40 + cg * 4;
            *(uint2*)(Ah + e) = make_uint2(h0, h1);
            *(uint2*)(Al + e) = make_uint2(l0, l1);
        }
        for (int i = tid; i < 1024; i += 256) {
            int row = i >> 5, cg = i & 31;
            float4 v = *(const float4*)(B + (size_t)(k0 + row) * N + n0 + cg * 4);
            uint32_t h0, l0, h1, l1;
            split_pack(v.x, v.y, h0, l0);
            split_pack(v.z, v.w, h1, l1);
            int e = row * 136 + cg * 4;
            *(uint2*)(Bh + e) = make_uint2(h0, h1);
            *(uint2*)(Bl + e) = make_uint2(l0, l1);
        }
        __syncthreads();

        #pragma unroll
        for (int ks = 0; ks < 2; ks++) {
            wmma::fragment<wmma::matrix_a, 16, 16, 16, __nv_bfloat16, wmma::row_major> ah[2], al[2];
            #pragma unroll
            for (int mi = 0; mi < 2; mi++) {
                wmma::load_matrix_sync(ah[mi], Ah + (mw * 32 + mi * 16) * 40 + ks * 16, 40);
                wmma::load_matrix_sync(al[mi], Al + (mw * 32 + mi * 16) * 40 + ks * 16, 40);
            }
            #pragma unroll
            for (int j = 0; j < 4; j++) {
                wmma::fragment<wmma::matrix_b, 16, 16, 16, __nv_bfloat16, wmma::row_major> bh, bl;
                wmma::load_matrix_sync(bh, Bh + ks * 16 * 136 + nw * 64 + j * 16, 136);
                wmma::load_matrix_sync(bl, Bl + ks * 16 * 136 + nw * 64 + j * 16, 136);
                #pragma unroll
                for (int mi = 0; mi < 2; mi++) {
                    wmma::mma_sync(acc[mi][j], ah[mi], bh, acc[mi][j]);
                    wmma::mma_sync(acc[mi][j], ah[mi], bl, acc[mi][j]);
                    wmma::mma_sync(acc[mi][j], al[mi], bh, acc[mi][j]);
                }
            }
        }
    }

    const int erow = tid >> 1, elc = (tid & 1) * 32;
    #pragma unroll
    for (int phse = 0; phse < 2; phse++) {
        __syncthreads();
        if (nw == phse) {
            #pragma unroll
            for (int mi = 0; mi < 2; mi++)
                #pragma unroll
                for (int j = 0; j < 4; j++)
                    wmma::store_matrix_sync(scratch + (mw * 32 + mi * 16) * 68 + j * 16,
                                            acc[mi][j], 68, wmma::mem_row_major);
        }
        __syncthreads();
        int gc0 = n0 + phse * 64 + elc;
        int m = m0 + erow;
        const float* sp = scratch + erow * 68 + elc;
        float* dst;
        if (MODE == 0) {
            int hh = gc0 >> 6, d = gc0 & 63;
            dst = C + ((size_t)hh * SEQ + m) * HD + d;
        } else {
            dst = C + (size_t)m * N + gc0;
        }
        #pragma unroll
        for (int j = 0; j < 32; j += 4) {
            float4 o;
            o.x = sp[j]     + bias[gc0 + j];
            o.y = sp[j + 1] + bias[gc0 + j + 1];
            o.z = sp[j + 2] + bias[gc0 + j + 2];
            o.w = sp[j + 3] + bias[gc0 + j + 3];
            *(float4*)(dst + j) = o;
        }
    }
}

// ---------------- K row-normalize ----------------
__global__ __launch_bounds__(256) void knorm_kernel(const float* __restrict__ K,
                                                    float* __restrict__ Kn)
{
    int row  = blockIdx.x * 8 + (threadIdx.x >> 5);
    int lane = threadIdx.x & 31;
    const float* kr = K + (size_t)row * HD;
    float v0 = kr[lane], v1 = kr[lane + 32];
    float ss = v0 * v0 + v1 * v1;
    #pragma unroll
    for (int o = 16; o; o >>= 1) ss += __shfl_xor_sync(0xffffffffu, ss, o);
    float inv = 1.f / fmaxf(sqrtf(ss), 1e-6f);
    Kn[(size_t)row * HD + lane]      = v0 * inv;
    Kn[(size_t)row * HD + lane + 32] = v1 * inv;
}

// ---------------- elementwise ----------------
// Vp = c0*V + c1*u
__global__ __launch_bounds__(256) void vp2_kernel(float* __restrict__ dst,
                                                  const float* __restrict__ a,
                                                  const float* __restrict__ b,
                                                  float c0, float c1)
{
    int i = blockIdx.x * 256 + threadIdx.x;
    float4 va = ((const float4*)a)[i];
    float4 vb = ((const float4*)b)[i];
    float4 o;
    o.x = c0 * va.x + c1 * vb.x; o.y = c0 * va.y + c1 * vb.y;
    o.z = c0 * va.z + c1 * vb.z; o.w = c0 * va.w + c1 * vb.w;
    ((float4*)dst)[i] = o;
}
__global__ __launch_bounds__(256) void axpy_kernel(float* __restrict__ dst,
                                                   const float* __restrict__ src, float c)
{
    int i = blockIdx.x * 256 + threadIdx.x;
    float4 v = ((const float4*)src)[i];
    float4 d = ((float4*)dst)[i];
    d.x = fmaf(c, v.x, d.x); d.y = fmaf(c, v.y, d.y);
    d.z = fmaf(c, v.z, d.z); d.w = fmaf(c, v.w, d.w);
    ((float4*)dst)[i] = d;
}

// ---------------- launch ----------------
extern "C" void kernel_launch(void* const* d_in, const int* in_sizes, int n_in,
                              void* d_out, int out_size)
{
    const float* X  = (const float*)d_in[0];
    const float* Wq = (const float*)d_in[1];
    const float* bq = (const float*)d_in[2];
    const float* Wk = (const float*)d_in[3];
    const float* bk = (const float*)d_in[4];
    const float* Wv = (const float*)d_in[5];
    const float* bv = (const float*)d_in[6];
    const float* Wo = (const float*)d_in[7];
    const float* bo = (const float*)d_in[8];

    float *Qd, *Kd, *Vd, *Knd, *ud, *u2d, *Vpd, *attnd;
    cudaGetSymbolAddress((void**)&Qd,    g_Q);
    cudaGetSymbolAddress((void**)&Kd,    g_K);
    cudaGetSymbolAddress((void**)&Vd,    g_V);
    cudaGetSymbolAddress((void**)&Knd,   g_Kn);
    cudaGetSymbolAddress((void**)&ud,    g_u);
    cudaGetSymbolAddress((void**)&u2d,   g_u2);
    cudaGetSymbolAddress((void**)&Vpd,   g_Vp);
    cudaGetSymbolAddress((void**)&attnd, g_attn);

    __nv_bfloat16 *bKnA, *bKnB, *bX, *bQh, *bQl, *bKh, *bKl, *bVh, *bVl;
    cudaGetSymbolAddress((void**)&bKnA, g_bKnA);
    cudaGetSymbolAddress((void**)&bKnB, g_bKnB);
    cudaGetSymbolAddress((void**)&bX,   g_bX);
    cudaGetSymbolAddress((void**)&bQh,  g_bQh);
    cudaGetSymbolAddress((void**)&bQl,  g_bQl);
    cudaGetSymbolAddress((void**)&bKh,  g_bKh);
    cudaGetSymbolAddress((void**)&bKl,  g_bKl);
    cudaGetSymbolAddress((void**)&bVh,  g_bVh);
    cudaGetSymbolAddress((void**)&bVl,  g_bVl);

    cudaFuncSetAttribute(attn_kernel<0>, cudaFuncAttributeMaxDynamicSharedMemorySize, SM0);
    cudaFuncSetAttribute(attn_kernel<1>, cudaFuncAttributeMaxDynamicSharedMemorySize, SM1);

    const float scl = 0.125f;           // 1/sqrt(64), TEMP=1
    const int NB = (TOT / 4) / 256;     // float4 grid
    dim3 gattn(SEQ / 64, NHEADS);

    // 1) fused Q/K/V projections (head-split outputs)
    dim3 gqkv(EMB / 128, SEQ / 128, 3);
    gemm_mma_kernel<0><<<gqkv, 256>>>(X, Wq, bq, Qd, Wk, bk, Kd, Wv, bv, Vd,
                                      SEQ, EMB, EMB);

    // 2) Kn = normalize(K); pre-convert operands
    knorm_kernel<<<(NHEADS * SEQ) / 8, 256>>>(Kd, Knd);
    cvt_kernel<0><<<NB, 256>>>(Knd, bKnA, nullptr, scl);   // A-side: scale folded
    cvt_kernel<0><<<NB, 256>>>(Knd, bKnB, nullptr, 1.0f);  // B-side
    cvt_kernel<0><<<NB, 256>>>(Vd,  bX,   nullptr, 1.0f);

    // 3) diffusion: V' = 0.98*(V + a*u1 + a^2*u2)   [a^3, a^4 terms < 1e-5: dropped]
    attn_kernel<0><<<gattn, 128, SM0>>>(bKnA, nullptr, bKnB, nullptr, bX, nullptr, ud, 0);
    vp2_kernel<<<NB, 256>>>(Vpd, Vd, ud, 0.98f, 0.98f * 0.02f);

    cvt_kernel<0><<<NB, 256>>>(ud, bX, nullptr, 1.0f);
    attn_kernel<0><<<gattn, 128, SM0>>>(bKnA, nullptr, bKnB, nullptr, bX, nullptr, u2d, 0);
    axpy_kernel<<<NB, 256>>>(Vpd, u2d, 0.98f * 0.0004f);

    // 4) final attention (split-3): out = softmax(QK^T/8) @ V'
    cvt_kernel<1><<<NB, 256>>>(Qd,  bQh, bQl, scl);        // scale folded into Q
    cvt_kernel<1><<<NB, 256>>>(Kd,  bKh, bKl, 1.0f);
    cvt_kernel<1><<<NB, 256>>>(Vpd, bVh, bVl, 1.0f);
    attn_kernel<1><<<gattn, 128, SM1>>>(bQh, bQl, bKh, bKl, bVh, bVl, attnd, 1);

    // 5) output projection -> d_out
    dim3 go(EMB / 128, SEQ / 128, 1);
    gemm_mma_kernel<1><<<go, 256>>>(attnd, Wo, bo, (float*)d_out,
                                    Wo, bo, (float*)d_out,
                                    Wo, bo, (float*)d_out,
                                    SEQ, EMB, EMB);
}

// round 5
// speedup vs baseline: 3.5737x; 1.4757x over previous
#include <cuda_runtime.h>
#include <cuda_bf16.h>
#include <mma.h>
#include <math.h>
#include <stdint.h>

using namespace nvcuda;

#define NHEADS 16
#define SEQ    2048
#define HD     64
#define EMB    1024
#define LHD    (SEQ*HD)
#define TOT    (NHEADS*SEQ*HD)

// ---------------- scratch (device globals; no allocations) ----------------
__device__ float g_Q[TOT];
__device__ float g_K[TOT];
__device__ float g_V[TOT];
__device__ float g_u[TOT];
__device__ float g_u2[TOT];
__device__ float g_Vp[TOT];
__device__ float g_attn[SEQ*EMB];
__device__ __nv_bfloat16 g_bKnA[TOT];
__device__ __nv_bfloat16 g_bKnB[TOT];
__device__ __nv_bfloat16 g_bX[TOT];
__device__ __nv_bfloat16 g_bQh[TOT], g_bQl[TOT];
__device__ __nv_bfloat16 g_bKh[TOT], g_bKl[TOT];
__device__ __nv_bfloat16 g_bVh[TOT], g_bVl[TOT];

// ---------------- helpers ----------------
__device__ __forceinline__ uint32_t pack2(__nv_bfloat16 a, __nv_bfloat16 b) {
    uint16_t x = *(uint16_t*)&a, y = *(uint16_t*)&b;
    return (uint32_t)x | ((uint32_t)y << 16);
}
__device__ __forceinline__ void split_pack(float a, float b, uint32_t& hi, uint32_t& lo) {
    __nv_bfloat16 ha = __float2bfloat16(a), hb = __float2bfloat16(b);
    float la = a - __bfloat162float(ha), lb = b - __bfloat162float(hb);
    hi = pack2(ha, hb);
    lo = pack2(__float2bfloat16(la), __float2bfloat16(lb));
}
__device__ __forceinline__ uint32_t smem_u32(const void* p) {
    uint32_t a;
    asm("{ .reg .u64 t; cvta.to.shared.u64 t, %1; cvt.u32.u64 %0, t; }" : "=r"(a) : "l"(p));
    return a;
}
__device__ __forceinline__ void ldsm4(uint32_t addr, uint32_t r[4]) {
    asm volatile("ldmatrix.sync.aligned.m8n8.x4.shared.b16 {%0,%1,%2,%3}, [%4];"
                 : "=r"(r[0]), "=r"(r[1]), "=r"(r[2]), "=r"(r[3]) : "r"(addr));
}
__device__ __forceinline__ void ldsm4t(uint32_t addr, uint32_t r[4]) {
    asm volatile("ldmatrix.sync.aligned.m8n8.x4.trans.shared.b16 {%0,%1,%2,%3}, [%4];"
                 : "=r"(r[0]), "=r"(r[1]), "=r"(r[2]), "=r"(r[3]) : "r"(addr));
}
__device__ __forceinline__ void mma16816(float d[4], const uint32_t a[4],
                                         uint32_t b0, uint32_t b1) {
    asm volatile(
        "mma.sync.aligned.m16n8k16.row.col.f32.bf16.bf16.f32 "
        "{%0,%1,%2,%3}, {%4,%5,%6,%7}, {%8,%9}, {%0,%1,%2,%3};"
        : "+f"(d[0]), "+f"(d[1]), "+f"(d[2]), "+f"(d[3])
        : "r"(a[0]), "r"(a[1]), "r"(a[2]), "r"(a[3]), "r"(b0), "r"(b1));
}
__device__ __forceinline__ void cp16(uint32_t s, const void* g) {
    asm volatile("cp.async.cg.shared.global [%0], [%1], 16;" :: "r"(s), "l"(g));
}
__device__ __forceinline__ void cp_commit() { asm volatile("cp.async.commit_group;"); }
__device__ __forceinline__ void cp_wait1() { asm volatile("cp.async.wait_group 1;" ::: "memory"); }
__device__ __forceinline__ void cp_wait0() { asm volatile("cp.async.wait_group 0;" ::: "memory"); }

// ---------------- fp32 -> bf16 (hi[, lo]) with scale ----------------
template<int HASLO>
__global__ __launch_bounds__(256) void cvt_kernel(const float* __restrict__ in,
                                                  __nv_bfloat16* __restrict__ hi,
                                                  __nv_bfloat16* __restrict__ lo,
                                                  float scale)
{
    int i = blockIdx.x * 256 + threadIdx.x;
    float4 v = ((const float4*)in)[i];
    v.x *= scale; v.y *= scale; v.z *= scale; v.w *= scale;
    uint32_t h0, l0, h1, l1;
    split_pack(v.x, v.y, h0, l0);
    split_pack(v.z, v.w, h1, l1);
    ((uint2*)hi)[i] = make_uint2(h0, h1);
    if (HASLO) ((uint2*)lo)[i] = make_uint2(l0, l1);
}

// ---------------- K normalize + convert (fused): a = bf16(Kn*scale), b = bf16(Kn) ----
__global__ __launch_bounds__(256) void knorm_cvt_kernel(const float* __restrict__ K,
                                                        __nv_bfloat16* __restrict__ a,
                                                        __nv_bfloat16* __restrict__ b,
                                                        float scale)
{
    int row  = blockIdx.x * 8 + (threadIdx.x >> 5);
    int lane = threadIdx.x & 31;
    const float* kr = K + (size_t)row * HD;
    float v0 = kr[lane], v1 = kr[lane + 32];
    float ss = v0 * v0 + v1 * v1;
    #pragma unroll
    for (int o = 16; o; o >>= 1) ss += __shfl_xor_sync(0xffffffffu, ss, o);
    float inv = 1.f / fmaxf(sqrtf(ss), 1e-6f);
    size_t e = (size_t)row * HD + lane;
    a[e]      = __float2bfloat16(v0 * inv * scale);
    a[e + 32] = __float2bfloat16(v1 * inv * scale);
    b[e]      = __float2bfloat16(v0 * inv);
    b[e + 32] = __float2bfloat16(v1 * inv);
}

// ============================================================================
// Raw-MMA flash attention, register-resident P, cp.async double buffering.
// O = softmax(A @ K^T) @ V  (scale pre-folded into A). SPLIT=1: hi/lo 3-term.
// grid (SEQ/64, NHEADS), 128 threads (4 warps; warp w owns q rows 16w..16w+15).
// ============================================================================
#define TBYTES 9216   // 64 x 72 bf16 tile

template<int SPLIT>
__global__ __launch_bounds__(128) void attn_kernel(
    const __nv_bfloat16* __restrict__ Ah, const __nv_bfloat16* __restrict__ Al,
    const __nv_bfloat16* __restrict__ Kg, const __nv_bfloat16* __restrict__ Kl,
    const __nv_bfloat16* __restrict__ Vg, const __nv_bfloat16* __restrict__ Vl,
    float* __restrict__ Og, int outmode)
{
    constexpr int NM = SPLIT ? 4 : 2;              // matrices per tile buffer
    constexpr int QBYTES = SPLIT ? 2 * TBYTES : TBYTES;
    extern __shared__ char sm[];
    const uint32_t sb = smem_u32(sm);

    const int tid = threadIdx.x;
    const int w = tid >> 5, lane = tid & 31;
    const int h = blockIdx.y, q0 = blockIdx.x * 64;

    const __nv_bfloat16* gmat[NM];
    if (SPLIT) { gmat[0] = Kg; gmat[1] = Kl; gmat[2] = Vg; gmat[3] = Vl; }
    else       { gmat[0] = Kg; gmat[1] = Vg; }
    const size_t hbase = (size_t)h * LHD;

    // ---- stage Q (regular stores) ----
    {
        const uint4* q4 = (const uint4*)(Ah + hbase + (size_t)q0 * HD);
        const uint4* q4l = SPLIT ? (const uint4*)(Al + hbase + (size_t)q0 * HD) : nullptr;
        #pragma unroll
        for (int i = 0; i < 4; i++) {
            int idx = tid + i * 128;
            int r = idx >> 3, c = idx & 7;
            *(uint4*)(sm + r * 144 + c * 16) = q4[idx];
            if (SPLIT) *(uint4*)(sm + TBYTES + r * 144 + c * 16) = q4l[idx];
        }
    }

    // ---- stage tile 0 via cp.async ----
    auto stage = [&](int kt, int b) {
        size_t base = hbase + (size_t)kt * (64 * HD);
        uint32_t sbuf = sb + QBYTES + b * NM * TBYTES;
        #pragma unroll
        for (int m = 0; m < NM; m++) {
            const __nv_bfloat16* g = gmat[m] + base;
            #pragma unroll
            for (int i = 0; i < 4; i++) {
                int idx = tid + i * 128;
                int r = idx >> 3, c = idx & 7;
                cp16(sbuf + m * TBYTES + r * 144 + c * 16, g + r * 64 + c * 8);
            }
        }
    };
    stage(0, 0);
    cp_commit();
    __syncthreads();   // Q visible

    // ---- persistent Q A-fragments ----
    uint32_t aQh[4][4], aQl[4][4];
    {
        uint32_t qaddr = sb + ((w * 16 + (lane & 15)) * 72 + 8 * (lane >> 4)) * 2;
        #pragma unroll
        for (int ks = 0; ks < 4; ks++) {
            ldsm4(qaddr + ks * 32, aQh[ks]);
            if (SPLIT) ldsm4(qaddr + TBYTES + ks * 32, aQl[ks]);
        }
    }

    float Oa[8][4];
    #pragma unroll
    for (int nt = 0; nt < 8; nt++)
        #pragma unroll
        for (int e = 0; e < 4; e++) Oa[nt][e] = 0.f;
    float ls0 = 0.f, ls1 = 0.f;

    const uint32_t koff = ((lane & 7) * 72 + 8 * (lane >> 3)) * 2;  // K ldsm lane offset
    const uint32_t voff = lane * 144;                               // V ldsm lane offset

    for (int kt = 0; kt < 32; kt++) {
        if (kt < 31) { stage(kt + 1, (kt + 1) & 1); cp_commit(); cp_wait1(); }
        else cp_wait0();
        __syncthreads();

        uint32_t buf = sb + QBYTES + (kt & 1) * NM * TBYTES;
        uint32_t bK  = buf;
        uint32_t bKl = buf + TBYTES;                      // SPLIT only
        uint32_t bV  = buf + (SPLIT ? 2 : 1) * TBYTES;
        uint32_t bVl = buf + 3 * TBYTES;                  // SPLIT only

        // ---- S = Q K^T  (8 n-tiles x 4 k-steps) ----
        float Sa[8][4];
        #pragma unroll
        for (int nt = 0; nt < 8; nt++) {
            #pragma unroll
            for (int e = 0; e < 4; e++) Sa[nt][e] = 0.f;
            #pragma unroll
            for (int kp = 0; kp < 2; kp++) {
                uint32_t bfr[4];
                ldsm4(bK + nt * 1152 + kp * 64 + koff, bfr);
                mma16816(Sa[nt], aQh[2 * kp],     bfr[0], bfr[1]);
                mma16816(Sa[nt], aQh[2 * kp + 1], bfr[2], bfr[3]);
                if (SPLIT) {
                    uint32_t bfl[4];
                    ldsm4(bKl + nt * 1152 + kp * 64 + koff, bfl);
                    mma16816(Sa[nt], aQh[2 * kp],     bfl[0], bfl[1]);
                    mma16816(Sa[nt], aQh[2 * kp + 1], bfl[2], bfl[3]);
                    mma16816(Sa[nt], aQl[2 * kp],     bfr[0], bfr[1]);
                    mma16816(Sa[nt], aQl[2 * kp + 1], bfr[2], bfr[3]);
                }
            }
        }

        // ---- exp in registers; pack P A-fragments; accumulate row sums ----
        uint32_t Ph[4][4], Pl[4][4];
        #pragma unroll
        for (int nt = 0; nt < 8; nt++) {
            float p0 = __expf(Sa[nt][0]), p1 = __expf(Sa[nt][1]);
            float p2 = __expf(Sa[nt][2]), p3 = __expf(Sa[nt][3]);
            ls0 += p0 + p1;
            ls1 += p2 + p3;
            int j = nt >> 1, hf = (nt & 1) * 2;
            if (SPLIT) {
                split_pack(p0, p1, Ph[j][hf + 0], Pl[j][hf + 0]);
                split_pack(p2, p3, Ph[j][hf + 1], Pl[j][hf + 1]);
            } else {
                Ph[j][hf + 0] = pack2(__float2bfloat16(p0), __float2bfloat16(p1));
                Ph[j][hf + 1] = pack2(__float2bfloat16(p2), __float2bfloat16(p3));
            }
        }

        // ---- O += P @ V  (8 n-tiles x 4 k-steps) ----
        #pragma unroll
        for (int nt = 0; nt < 8; nt++) {
            #pragma unroll
            for (int kp = 0; kp < 2; kp++) {
                uint32_t vfr[4];
                ldsm4t(bV + kp * 4608 + voff + nt * 16, vfr);
                mma16816(Oa[nt], Ph[2 * kp],     vfr[0], vfr[1]);
                mma16816(Oa[nt], Ph[2 * kp + 1], vfr[2], vfr[3]);
                if (SPLIT) {
                    uint32_t vfl[4];
                    ldsm4t(bVl + kp * 4608 + voff + nt * 16, vfl);
                    mma16816(Oa[nt], Ph[2 * kp],     vfl[0], vfl[1]);
                    mma16816(Oa[nt], Ph[2 * kp + 1], vfl[2], vfl[3]);
                    mma16816(Oa[nt], Pl[2 * kp],     vfr[0], vfr[1]);
                    mma16816(Oa[nt], Pl[2 * kp + 1], vfr[2], vfr[3]);
                }
            }
        }
        __syncthreads();   // compute done before next stage overwrites this buffer
    }

    // ---- epilogue: quad-reduce row sums, normalize, write ----
    ls0 += __shfl_xor_sync(0xffffffffu, ls0, 1);
    ls0 += __shfl_xor_sync(0xffffffffu, ls0, 2);
    ls1 += __shfl_xor_sync(0xffffffffu, ls1, 1);
    ls1 += __shfl_xor_sync(0xffffffffu, ls1, 2);
    float inv0 = 1.f / ls0, inv1 = 1.f / ls1;

    int r = lane >> 2, c2 = (lane & 3) * 2;
    int row0 = q0 + w * 16 + r, row1 = row0 + 8;
    float* d0 = outmode ? Og + (size_t)row0 * EMB + h * HD
                        : Og + ((size_t)h * SEQ + row0) * HD;
    float* d1 = outmode ? Og + (size_t)row1 * EMB + h * HD
                        : Og + ((size_t)h * SEQ + row1) * HD;
    #pragma unroll
    for (int nt = 0; nt < 8; nt++) {
        int col = 8 * nt + c2;
        float2 o0 = make_float2(Oa[nt][0] * inv0, Oa[nt][1] * inv0);
        float2 o1 = make_float2(Oa[nt][2] * inv1, Oa[nt][3] * inv1);
        *(float2*)(d0 + col) = o0;
        *(float2*)(d1 + col) = o1;
    }
}
#define SM_ATTN0 (TBYTES + 2 * 2 * TBYTES)       // 46080
#define SM_ATTN1 (2 * TBYTES + 2 * 4 * TBYTES)   // 92160

// ============================================================================
// WMMA split-3 GEMM (unchanged): C = A(MxK) @ B(KxN) + bias
// ============================================================================
template<int MODE>
__global__ __launch_bounds__(256) void gemm_mma_kernel(
    const float* __restrict__ A,
    const float* __restrict__ B0, const float* __restrict__ bias0, float* __restrict__ C0,
    const float* __restrict__ B1, const float* __restrict__ bias1, float* __restrict__ C1,
    const float* __restrict__ B2, const float* __restrict__ bias2, float* __restrict__ C2,
    int M, int N, int K)
{
    const float* B; const float* bias; float* C;
    if (blockIdx.z == 0)      { B = B0; bias = bias0; C = C0; }
    else if (blockIdx.z == 1) { B = B1; bias = bias1; C = C1; }
    else                      { B = B2; bias = bias2; C = C2; }

    __shared__ __align__(16) char smb[37888];
    __nv_bfloat16* Ah = (__nv_bfloat16*)smb;
    __nv_bfloat16* Al = Ah + 5120;
    __nv_bfloat16* Bh = Al + 5120;
    __nv_bfloat16* Bl = Bh + 4352;
    float* scratch = (float*)smb;

    const int tid = threadIdx.x;
    const int w = tid >> 5;
    const int mw = w & 3, nw = w >> 2;
    const int m0 = blockIdx.y * 128, n0 = blockIdx.x * 128;

    wmma::fragment<wmma::accumulator, 16, 16, 16, float> acc[2][4];
    #pragma unroll
    for (int mi = 0; mi < 2; mi++)
        #pragma unroll
        for (int j = 0; j < 4; j++) wmma::fill_fragment(acc[mi][j], 0.f);

    for (int k0 = 0; k0 < K; k0 += 32) {
        __syncthreads();
        for (int i = tid; i < 1024; i += 256) {
            int row = i >> 3, cg = i & 7;
            float4 v = *(const float4*)(A + (size_t)(m0 + row) * K + k0 + cg * 4);
            uint32_t h0, l0, h1, l1;
            split_pack(v.x, v.y, h0, l0);
            split_pack(v.z, v.w, h1, l1);
            int e = row * 40 + cg * 4;
            *(uint2*)(Ah + e) = make_uint2(h0, h1);
            *(uint2*)(Al + e) = make_uint2(l0, l1);
        }
        for (int i = tid; i < 1024; i += 256) {
            int row = i >> 5, cg = i & 31;
            float4 v = *(const float4*)(B + (size_t)(k0 + row) * N + n0 + cg * 4);
            uint32_t h0, l0, h1, l1;
            split_pack(v.x, v.y, h0, l0);
            split_pack(v.z, v.w, h1, l1);
            int e = row * 136 + cg * 4;
            *(uint2*)(Bh + e) = make_uint2(h0, h1);
            *(uint2*)(Bl + e) = make_uint2(l0, l1);
        }
        __syncthreads();

        #pragma unroll
        for (int ks = 0; ks < 2; ks++) {
            wmma::fragment<wmma::matrix_a, 16, 16, 16, __nv_bfloat16, wmma::row_major> ah[2], al[2];
            #pragma unroll
            for (int mi = 0; mi < 2; mi++) {
                wmma::load_matrix_sync(ah[mi], Ah + (mw * 32 + mi * 16) * 40 + ks * 16, 40);
                wmma::load_matrix_sync(al[mi], Al + (mw * 32 + mi * 16) * 40 + ks * 16, 40);
            }
            #pragma unroll
            for (int j = 0; j < 4; j++) {
                wmma::fragment<wmma::matrix_b, 16, 16, 16, __nv_bfloat16, wmma::row_major> bh, bl;
                wmma::load_matrix_sync(bh, Bh + ks * 16 * 136 + nw * 64 + j * 16, 136);
                wmma::load_matrix_sync(bl, Bl + ks * 16 * 136 + nw * 64 + j * 16, 136);
                #pragma unroll
                for (int mi = 0; mi < 2; mi++) {
                    wmma::mma_sync(acc[mi][j], ah[mi], bh, acc[mi][j]);
                    wmma::mma_sync(acc[mi][j], ah[mi], bl, acc[mi][j]);
                    wmma::mma_sync(acc[mi][j], al[mi], bh, acc[mi][j]);
                }
            }
        }
    }

    const int erow = tid >> 1, elc = (tid & 1) * 32;
    #pragma unroll
    for (int phse = 0; phse < 2; phse++) {
        __syncthreads();
        if (nw == phse) {
            #pragma unroll
            for (int mi = 0; mi < 2; mi++)
                #pragma unroll
                for (int j = 0; j < 4; j++)
                    wmma::store_matrix_sync(scratch + (mw * 32 + mi * 16) * 68 + j * 16,
                                            acc[mi][j], 68, wmma::mem_row_major);
        }
        __syncthreads();
        int gc0 = n0 + phse * 64 + elc;
        int m = m0 + erow;
        const float* sp = scratch + erow * 68 + elc;
        float* dst;
        if (MODE == 0) {
            int hh = gc0 >> 6, d = gc0 & 63;
            dst = C + ((size_t)hh * SEQ + m) * HD + d;
        } else {
            dst = C + (size_t)m * N + gc0;
        }
        #pragma unroll
        for (int j = 0; j < 32; j += 4) {
            float4 o;
            o.x = sp[j]     + bias[gc0 + j];
            o.y = sp[j + 1] + bias[gc0 + j + 1];
            o.z = sp[j + 2] + bias[gc0 + j + 2];
            o.w = sp[j + 3] + bias[gc0 + j + 3];
            *(float4*)(dst + j) = o;
        }
    }
}

// ---------------- elementwise ----------------
__global__ __launch_bounds__(256) void vp2_kernel(float* __restrict__ dst,
                                                  const float* __restrict__ a,
                                                  const float* __restrict__ b,
                                                  float c0, float c1)
{
    int i = blockIdx.x * 256 + threadIdx.x;
    float4 va = ((const float4*)a)[i];
    float4 vb = ((const float4*)b)[i];
    float4 o;
    o.x = c0 * va.x + c1 * vb.x; o.y = c0 * va.y + c1 * vb.y;
    o.z = c0 * va.z + c1 * vb.z; o.w = c0 * va.w + c1 * vb.w;
    ((float4*)dst)[i] = o;
}
__global__ __launch_bounds__(256) void axpy_kernel(float* __restrict__ dst,
                                                   const float* __restrict__ src, float c)
{
    int i = blockIdx.x * 256 + threadIdx.x;
    float4 v = ((const float4*)src)[i];
    float4 d = ((float4*)dst)[i];
    d.x = fmaf(c, v.x, d.x); d.y = fmaf(c, v.y, d.y);
    d.z = fmaf(c, v.z, d.z); d.w = fmaf(c, v.w, d.w);
    ((float4*)dst)[i] = d;
}

// ---------------- launch ----------------
extern "C" void kernel_launch(void* const* d_in, const int* in_sizes, int n_in,
                              void* d_out, int out_size)
{
    const float* X  = (const float*)d_in[0];
    const float* Wq = (const float*)d_in[1];
    const float* bq = (const float*)d_in[2];
    const float* Wk = (const float*)d_in[3];
    const float* bk = (const float*)d_in[4];
    const float* Wv = (const float*)d_in[5];
    const float* bv = (const float*)d_in[6];
    const float* Wo = (const float*)d_in[7];
    const float* bo = (const float*)d_in[8];

    float *Qd, *Kd, *Vd, *ud, *u2d, *Vpd, *attnd;
    cudaGetSymbolAddress((void**)&Qd,    g_Q);
    cudaGetSymbolAddress((void**)&Kd,    g_K);
    cudaGetSymbolAddress((void**)&Vd,    g_V);
    cudaGetSymbolAddress((void**)&ud,    g_u);
    cudaGetSymbolAddress((void**)&u2d,   g_u2);
    cudaGetSymbolAddress((void**)&Vpd,   g_Vp);
    cudaGetSymbolAddress((void**)&attnd, g_attn);

    __nv_bfloat16 *bKnA, *bKnB, *bX, *bQh, *bQl, *bKh, *bKl, *bVh, *bVl;
    cudaGetSymbolAddress((void**)&bKnA, g_bKnA);
    cudaGetSymbolAddress((void**)&bKnB, g_bKnB);
    cudaGetSymbolAddress((void**)&bX,   g_bX);
    cudaGetSymbolAddress((void**)&bQh,  g_bQh);
    cudaGetSymbolAddress((void**)&bQl,  g_bQl);
    cudaGetSymbolAddress((void**)&bKh,  g_bKh);
    cudaGetSymbolAddress((void**)&bKl,  g_bKl);
    cudaGetSymbolAddress((void**)&bVh,  g_bVh);
    cudaGetSymbolAddress((void**)&bVl,  g_bVl);

    cudaFuncSetAttribute(attn_kernel<0>, cudaFuncAttributeMaxDynamicSharedMemorySize, SM_ATTN0);
    cudaFuncSetAttribute(attn_kernel<1>, cudaFuncAttributeMaxDynamicSharedMemorySize, SM_ATTN1);

    const float scl = 0.125f;
    const int NB = (TOT / 4) / 256;
    dim3 gattn(SEQ / 64, NHEADS);

    // 1) fused Q/K/V projections (head-split outputs)
    dim3 gqkv(EMB / 128, SEQ / 128, 3);
    gemm_mma_kernel<0><<<gqkv, 256>>>(X, Wq, bq, Qd, Wk, bk, Kd, Wv, bv, Vd,
                                      SEQ, EMB, EMB);

    // 2) fused normalize + convert: bKnA = bf16(Kn/8), bKnB = bf16(Kn)
    knorm_cvt_kernel<<<(NHEADS * SEQ) / 8, 256>>>(Kd, bKnA, bKnB, scl);
    cvt_kernel<0><<<NB, 256>>>(Vd, bX, nullptr, 1.0f);

    // 3) diffusion: V' = 0.98*(V + a*u1 + a^2*u2)
    attn_kernel<0><<<gattn, 128, SM_ATTN0>>>(bKnA, nullptr, bKnB, nullptr, bX, nullptr, ud, 0);
    vp2_kernel<<<NB, 256>>>(Vpd, Vd, ud, 0.98f, 0.98f * 0.02f);

    cvt_kernel<0><<<NB, 256>>>(ud, bX, nullptr, 1.0f);
    attn_kernel<0><<<gattn, 128, SM_ATTN0>>>(bKnA, nullptr, bKnB, nullptr, bX, nullptr, u2d, 0);
    axpy_kernel<<<NB, 256>>>(Vpd, u2d, 0.98f * 0.0004f);

    // 4) final attention (split-3): out = softmax(QK^T/8) @ V'
    cvt_kernel<1><<<NB, 256>>>(Qd,  bQh, bQl, scl);
    cvt_kernel<1><<<NB, 256>>>(Kd,  bKh, bKl, 1.0f);
    cvt_kernel<1><<<NB, 256>>>(Vpd, bVh, bVl, 1.0f);
    attn_kernel<1><<<gattn, 128, SM_ATTN1>>>(bQh, bQl, bKh, bKl, bVh, bVl, attnd, 1);

    // 5) output projection -> d_out
    dim3 go(EMB / 128, SEQ / 128, 1);
    gemm_mma_kernel<1><<<go, 256>>>(attnd, Wo, bo, (float*)d_out,
                                    Wo, bo, (float*)d_out,
                                    Wo, bo, (float*)d_out,
                                    SEQ, EMB, EMB);
}

// round 6
// speedup vs baseline: 5.9170x; 1.6557x over previous
#include <cuda_runtime.h>
#include <cuda_bf16.h>
#include <math.h>
#include <stdint.h>

#define NHEADS 16
#define SEQ    2048
#define HD     64
#define EMB    1024
#define LHD    (SEQ*HD)
#define TOT    (NHEADS*SEQ*HD)

// ---------------- scratch (device globals; no allocations) ----------------
__device__ float g_Q[TOT];
__device__ float g_K[TOT];
__device__ float g_V[TOT];
__device__ float g_u[TOT];
__device__ float g_u2[TOT];
__device__ float g_Vp[TOT];
__device__ float g_attn[SEQ*EMB];
__device__ __nv_bfloat16 g_bKnA[TOT];
__device__ __nv_bfloat16 g_bKnB[TOT];
__device__ __nv_bfloat16 g_bX[TOT];
__device__ __nv_bfloat16 g_bQh[TOT], g_bQl[TOT];
__device__ __nv_bfloat16 g_bKh[TOT], g_bKl[TOT];
__device__ __nv_bfloat16 g_bVh[TOT], g_bVl[TOT];
// GEMM operand buffers (bf16 hi/lo)
__device__ __nv_bfloat16 g_bXh[SEQ*EMB], g_bXl[SEQ*EMB];
__device__ __nv_bfloat16 g_bWqh[EMB*EMB], g_bWql[EMB*EMB];
__device__ __nv_bfloat16 g_bWkh[EMB*EMB], g_bWkl[EMB*EMB];
__device__ __nv_bfloat16 g_bWvh[EMB*EMB], g_bWvl[EMB*EMB];
__device__ __nv_bfloat16 g_bWoh[EMB*EMB], g_bWol[EMB*EMB];
__device__ __nv_bfloat16 g_bAh[SEQ*EMB], g_bAl[SEQ*EMB];

// ---------------- helpers ----------------
__device__ __forceinline__ uint32_t pack2(__nv_bfloat16 a, __nv_bfloat16 b) {
    uint16_t x = *(uint16_t*)&a, y = *(uint16_t*)&b;
    return (uint32_t)x | ((uint32_t)y << 16);
}
__device__ __forceinline__ void split_pack(float a, float b, uint32_t& hi, uint32_t& lo) {
    __nv_bfloat16 ha = __float2bfloat16(a), hb = __float2bfloat16(b);
    float la = a - __bfloat162float(ha), lb = b - __bfloat162float(hb);
    hi = pack2(ha, hb);
    lo = pack2(__float2bfloat16(la), __float2bfloat16(lb));
}
__device__ __forceinline__ uint32_t smem_u32(const void* p) {
    uint32_t a;
    asm("{ .reg .u64 t; cvta.to.shared.u64 t, %1; cvt.u32.u64 %0, t; }" : "=r"(a) : "l"(p));
    return a;
}
__device__ __forceinline__ void ldsm4(uint32_t addr, uint32_t r[4]) {
    asm volatile("ldmatrix.sync.aligned.m8n8.x4.shared.b16 {%0,%1,%2,%3}, [%4];"
                 : "=r"(r[0]), "=r"(r[1]), "=r"(r[2]), "=r"(r[3]) : "r"(addr));
}
__device__ __forceinline__ void ldsm4t(uint32_t addr, uint32_t r[4]) {
    asm volatile("ldmatrix.sync.aligned.m8n8.x4.trans.shared.b16 {%0,%1,%2,%3}, [%4];"
                 : "=r"(r[0]), "=r"(r[1]), "=r"(r[2]), "=r"(r[3]) : "r"(addr));
}
__device__ __forceinline__ void mma16816(float d[4], const uint32_t a[4],
                                         uint32_t b0, uint32_t b1) {
    asm volatile(
        "mma.sync.aligned.m16n8k16.row.col.f32.bf16.bf16.f32 "
        "{%0,%1,%2,%3}, {%4,%5,%6,%7}, {%8,%9}, {%0,%1,%2,%3};"
        : "+f"(d[0]), "+f"(d[1]), "+f"(d[2]), "+f"(d[3])
        : "r"(a[0]), "r"(a[1]), "r"(a[2]), "r"(a[3]), "r"(b0), "r"(b1));
}
__device__ __forceinline__ void cp16(uint32_t s, const void* g) {
    asm volatile("cp.async.cg.shared.global [%0], [%1], 16;" :: "r"(s), "l"(g));
}
__device__ __forceinline__ void cp_commit() { asm volatile("cp.async.commit_group;"); }
__device__ __forceinline__ void cp_wait1() { asm volatile("cp.async.wait_group 1;" ::: "memory"); }
__device__ __forceinline__ void cp_wait0() { asm volatile("cp.async.wait_group 0;" ::: "memory"); }

// ---------------- fp32 -> bf16 (hi[, lo]) with scale ----------------
template<int HASLO>
__global__ __launch_bounds__(256) void cvt_kernel(const float* __restrict__ in,
                                                  __nv_bfloat16* __restrict__ hi,
                                                  __nv_bfloat16* __restrict__ lo,
                                                  float scale)
{
    int i = blockIdx.x * 256 + threadIdx.x;
    float4 v = ((const float4*)in)[i];
    v.x *= scale; v.y *= scale; v.z *= scale; v.w *= scale;
    uint32_t h0, l0, h1, l1;
    split_pack(v.x, v.y, h0, l0);
    split_pack(v.z, v.w, h1, l1);
    ((uint2*)hi)[i] = make_uint2(h0, h1);
    if (HASLO) ((uint2*)lo)[i] = make_uint2(l0, l1);
}

// ---------------- K normalize + convert (fused) ----------------
__global__ __launch_bounds__(256) void knorm_cvt_kernel(const float* __restrict__ K,
                                                        __nv_bfloat16* __restrict__ a,
                                                        __nv_bfloat16* __restrict__ b,
                                                        float scale)
{
    int row  = blockIdx.x * 8 + (threadIdx.x >> 5);
    int lane = threadIdx.x & 31;
    const float* kr = K + (size_t)row * HD;
    float v0 = kr[lane], v1 = kr[lane + 32];
    float ss = v0 * v0 + v1 * v1;
    #pragma unroll
    for (int o = 16; o; o >>= 1) ss += __shfl_xor_sync(0xffffffffu, ss, o);
    float inv = 1.f / fmaxf(sqrtf(ss), 1e-6f);
    size_t e = (size_t)row * HD + lane;
    a[e]      = __float2bfloat16(v0 * inv * scale);
    a[e + 32] = __float2bfloat16(v1 * inv * scale);
    b[e]      = __float2bfloat16(v0 * inv);
    b[e + 32] = __float2bfloat16(v1 * inv);
}

// ============================================================================
// Raw-MMA flash attention (unchanged from R5)
// ============================================================================
#define TBYTES 9216   // 64 x 72 bf16 tile

template<int SPLIT>
__global__ __launch_bounds__(128) void attn_kernel(
    const __nv_bfloat16* __restrict__ Ah, const __nv_bfloat16* __restrict__ Al,
    const __nv_bfloat16* __restrict__ Kg, const __nv_bfloat16* __restrict__ Kl,
    const __nv_bfloat16* __restrict__ Vg, const __nv_bfloat16* __restrict__ Vl,
    float* __restrict__ Og, int outmode)
{
    constexpr int NM = SPLIT ? 4 : 2;
    constexpr int QBYTES = SPLIT ? 2 * TBYTES : TBYTES;
    extern __shared__ char sm[];
    const uint32_t sb = smem_u32(sm);

    const int tid = threadIdx.x;
    const int w = tid >> 5, lane = tid & 31;
    const int h = blockIdx.y, q0 = blockIdx.x * 64;

    const __nv_bfloat16* gmat[NM];
    if (SPLIT) { gmat[0] = Kg; gmat[1] = Kl; gmat[2] = Vg; gmat[3] = Vl; }
    else       { gmat[0] = Kg; gmat[1] = Vg; }
    const size_t hbase = (size_t)h * LHD;

    {
        const uint4* q4 = (const uint4*)(Ah + hbase + (size_t)q0 * HD);
        const uint4* q4l = SPLIT ? (const uint4*)(Al + hbase + (size_t)q0 * HD) : nullptr;
        #pragma unroll
        for (int i = 0; i < 4; i++) {
            int idx = tid + i * 128;
            int r = idx >> 3, c = idx & 7;
            *(uint4*)(sm + r * 144 + c * 16) = q4[idx];
            if (SPLIT) *(uint4*)(sm + TBYTES + r * 144 + c * 16) = q4l[idx];
        }
    }

    auto stage = [&](int kt, int b) {
        size_t base = hbase + (size_t)kt * (64 * HD);
        uint32_t sbuf = sb + QBYTES + b * NM * TBYTES;
        #pragma unroll
        for (int m = 0; m < NM; m++) {
            const __nv_bfloat16* g = gmat[m] + base;
            #pragma unroll
            for (int i = 0; i < 4; i++) {
                int idx = tid + i * 128;
                int r = idx >> 3, c = idx & 7;
                cp16(sbuf + m * TBYTES + r * 144 + c * 16, g + r * 64 + c * 8);
            }
        }
    };
    stage(0, 0);
    cp_commit();
    __syncthreads();

    uint32_t aQh[4][4], aQl[4][4];
    {
        uint32_t qaddr = sb + ((w * 16 + (lane & 15)) * 72 + 8 * (lane >> 4)) * 2;
        #pragma unroll
        for (int ks = 0; ks < 4; ks++) {
            ldsm4(qaddr + ks * 32, aQh[ks]);
            if (SPLIT) ldsm4(qaddr + TBYTES + ks * 32, aQl[ks]);
        }
    }

    float Oa[8][4];
    #pragma unroll
    for (int nt = 0; nt < 8; nt++)
        #pragma unroll
        for (int e = 0; e < 4; e++) Oa[nt][e] = 0.f;
    float ls0 = 0.f, ls1 = 0.f;

    const uint32_t koff = ((lane & 7) * 72 + 8 * (lane >> 3)) * 2;
    const uint32_t voff = lane * 144;

    for (int kt = 0; kt < 32; kt++) {
        if (kt < 31) { stage(kt + 1, (kt + 1) & 1); cp_commit(); cp_wait1(); }
        else cp_wait0();
        __syncthreads();

        uint32_t buf = sb + QBYTES + (kt & 1) * NM * TBYTES;
        uint32_t bK  = buf;
        uint32_t bKl = buf + TBYTES;
        uint32_t bV  = buf + (SPLIT ? 2 : 1) * TBYTES;
        uint32_t bVl = buf + 3 * TBYTES;

        float Sa[8][4];
        #pragma unroll
        for (int nt = 0; nt < 8; nt++) {
            #pragma unroll
            for (int e = 0; e < 4; e++) Sa[nt][e] = 0.f;
            #pragma unroll
            for (int kp = 0; kp < 2; kp++) {
                uint32_t bfr[4];
                ldsm4(bK + nt * 1152 + kp * 64 + koff, bfr);
                mma16816(Sa[nt], aQh[2 * kp],     bfr[0], bfr[1]);
                mma16816(Sa[nt], aQh[2 * kp + 1], bfr[2], bfr[3]);
                if (SPLIT) {
                    uint32_t bfl[4];
                    ldsm4(bKl + nt * 1152 + kp * 64 + koff, bfl);
                    mma16816(Sa[nt], aQh[2 * kp],     bfl[0], bfl[1]);
                    mma16816(Sa[nt], aQh[2 * kp + 1], bfl[2], bfl[3]);
                    mma16816(Sa[nt], aQl[2 * kp],     bfr[0], bfr[1]);
                    mma16816(Sa[nt], aQl[2 * kp + 1], bfr[2], bfr[3]);
                }
            }
        }

        uint32_t Ph[4][4], Pl[4][4];
        #pragma unroll
        for (int nt = 0; nt < 8; nt++) {
            float p0 = __expf(Sa[nt][0]), p1 = __expf(Sa[nt][1]);
            float p2 = __expf(Sa[nt][2]), p3 = __expf(Sa[nt][3]);
            ls0 += p0 + p1;
            ls1 += p2 + p3;
            int j = nt >> 1, hf = (nt & 1) * 2;
            if (SPLIT) {
                split_pack(p0, p1, Ph[j][hf + 0], Pl[j][hf + 0]);
                split_pack(p2, p3, Ph[j][hf + 1], Pl[j][hf + 1]);
            } else {
                Ph[j][hf + 0] = pack2(__float2bfloat16(p0), __float2bfloat16(p1));
                Ph[j][hf + 1] = pack2(__float2bfloat16(p2), __float2bfloat16(p3));
            }
        }

        #pragma unroll
        for (int nt = 0; nt < 8; nt++) {
            #pragma unroll
            for (int kp = 0; kp < 2; kp++) {
                uint32_t vfr[4];
                ldsm4t(bV + kp * 4608 + voff + nt * 16, vfr);
                mma16816(Oa[nt], Ph[2 * kp],     vfr[0], vfr[1]);
                mma16816(Oa[nt], Ph[2 * kp + 1], vfr[2], vfr[3]);
                if (SPLIT) {
                    uint32_t vfl[4];
                    ldsm4t(bVl + kp * 4608 + voff + nt * 16, vfl);
                    mma16816(Oa[nt], Ph[2 * kp],     vfl[0], vfl[1]);
                    mma16816(Oa[nt], Ph[2 * kp + 1], vfl[2], vfl[3]);
                    mma16816(Oa[nt], Pl[2 * kp],     vfr[0], vfr[1]);
                    mma16816(Oa[nt], Pl[2 * kp + 1], vfr[2], vfr[3]);
                }
            }
        }
        __syncthreads();
    }

    ls0 += __shfl_xor_sync(0xffffffffu, ls0, 1);
    ls0 += __shfl_xor_sync(0xffffffffu, ls0, 2);
    ls1 += __shfl_xor_sync(0xffffffffu, ls1, 1);
    ls1 += __shfl_xor_sync(0xffffffffu, ls1, 2);
    float inv0 = 1.f / ls0, inv1 = 1.f / ls1;

    int r = lane >> 2, c2 = (lane & 3) * 2;
    int row0 = q0 + w * 16 + r, row1 = row0 + 8;
    float* d0 = outmode ? Og + (size_t)row0 * EMB + h * HD
                        : Og + ((size_t)h * SEQ + row0) * HD;
    float* d1 = outmode ? Og + (size_t)row1 * EMB + h * HD
                        : Og + ((size_t)h * SEQ + row1) * HD;
    #pragma unroll
    for (int nt = 0; nt < 8; nt++) {
        int col = 8 * nt + c2;
        *(float2*)(d0 + col) = make_float2(Oa[nt][0] * inv0, Oa[nt][1] * inv0);
        *(float2*)(d1 + col) = make_float2(Oa[nt][2] * inv1, Oa[nt][3] * inv1);
    }
}
#define SM_ATTN0 (TBYTES + 2 * 2 * TBYTES)
#define SM_ATTN1 (2 * TBYTES + 2 * 4 * TBYTES)

// ============================================================================
// Raw-MMA split-3 GEMM, pre-converted bf16 operands, cp.async double buffer.
// C = A(MxK) @ B(KxN) + bias.  MODE 0: head-split C[h][m][d]; 1: row-major.
// blockIdx.z selects (B,bias,C) triple. Tile 128x128, kstep 32, 256 thr.
// ============================================================================
#define GA_H 0          // A 128x40 bf16 (10240B)
#define GA_L 10240
#define GB_H 20480      // B 32x136 bf16 (8704B)
#define GB_L 29184
#define GSTG 37888      // stage stride
#define GSM  (2 * GSTG) // 75776

template<int MODE>
__global__ __launch_bounds__(256) void gemm_raw_kernel(
    const __nv_bfloat16* __restrict__ Ahg, const __nv_bfloat16* __restrict__ Alg,
    const __nv_bfloat16* __restrict__ B0h, const __nv_bfloat16* __restrict__ B0l,
    const float* __restrict__ bias0, float* __restrict__ C0,
    const __nv_bfloat16* __restrict__ B1h, const __nv_bfloat16* __restrict__ B1l,
    const float* __restrict__ bias1, float* __restrict__ C1,
    const __nv_bfloat16* __restrict__ B2h, const __nv_bfloat16* __restrict__ B2l,
    const float* __restrict__ bias2, float* __restrict__ C2,
    int M, int N, int K)
{
    const __nv_bfloat16 *Bhg, *Blg; const float* bias; float* C;
    if (blockIdx.z == 0)      { Bhg = B0h; Blg = B0l; bias = bias0; C = C0; }
    else if (blockIdx.z == 1) { Bhg = B1h; Blg = B1l; bias = bias1; C = C1; }
    else                      { Bhg = B2h; Blg = B2l; bias = bias2; C = C2; }

    extern __shared__ char sm[];
    const uint32_t sb = smem_u32(sm);

    const int tid = threadIdx.x;
    const int w = tid >> 5, lane = tid & 31;
    const int mw = w & 3, nw = w >> 2;
    const int m0 = blockIdx.y * 128, n0 = blockIdx.x * 128;

    auto stage = [&](int k0, int b) {
        uint32_t buf = sb + b * GSTG;
        // A tiles 128x32 hi+lo: 1024 x 16B
        #pragma unroll
        for (int i = 0; i < 4; i++) {
            int idx = tid + i * 256;
            int hl = idx >> 9, j = idx & 511;
            int r = j >> 2, c = j & 3;
            const __nv_bfloat16* g = (hl ? Alg : Ahg) + (size_t)(m0 + r) * K + k0 + c * 8;
            cp16(buf + (hl ? GA_L : GA_H) + r * 80 + c * 16, g);
        }
        // B tiles 32x128 hi+lo: 1024 x 16B
        #pragma unroll
        for (int i = 0; i < 4; i++) {
            int idx = tid + i * 256;
            int hl = idx >> 9, j = idx & 511;
            int r = j >> 4, c = j & 15;
            const __nv_bfloat16* g = (hl ? Blg : Bhg) + (size_t)(k0 + r) * N + n0 + c * 8;
            cp16(buf + (hl ? GB_L : GB_H) + r * 272 + c * 16, g);
        }
    };

    float acc[2][8][4];
    #pragma unroll
    for (int mi = 0; mi < 2; mi++)
        #pragma unroll
        for (int nt = 0; nt < 8; nt++)
            #pragma unroll
            for (int e = 0; e < 4; e++) acc[mi][nt][e] = 0.f;

    stage(0, 0);
    cp_commit();

    const uint32_t aoff = ((lane & 15) * 40 + (lane >> 4) * 8) * 2;
    const uint32_t boff = lane * 272 + (nw * 64) * 2;

    const int NK = K / 32;
    for (int ki = 0; ki < NK; ki++) {
        if (ki < NK - 1) { stage((ki + 1) * 32, (ki + 1) & 1); cp_commit(); cp_wait1(); }
        else cp_wait0();
        __syncthreads();

        uint32_t buf = sb + (ki & 1) * GSTG;

        uint32_t aH[2][2][4], aL[2][2][4];
        #pragma unroll
        for (int mi = 0; mi < 2; mi++) {
            uint32_t abase = buf + (mw * 32 + mi * 16) * 80 + aoff;
            #pragma unroll
            for (int kc = 0; kc < 2; kc++) {
                ldsm4(abase + GA_H + kc * 32, aH[mi][kc]);
                ldsm4(abase + GA_L + kc * 32, aL[mi][kc]);
            }
        }
        #pragma unroll
        for (int nt = 0; nt < 8; nt++) {
            uint32_t bfr[4], bfl[4];
            ldsm4t(buf + GB_H + boff + nt * 16, bfr);
            ldsm4t(buf + GB_L + boff + nt * 16, bfl);
            #pragma unroll
            for (int mi = 0; mi < 2; mi++) {
                mma16816(acc[mi][nt], aH[mi][0], bfr[0], bfr[1]);
                mma16816(acc[mi][nt], aH[mi][1], bfr[2], bfr[3]);
                mma16816(acc[mi][nt], aH[mi][0], bfl[0], bfl[1]);
                mma16816(acc[mi][nt], aH[mi][1], bfl[2], bfl[3]);
                mma16816(acc[mi][nt], aL[mi][0], bfr[0], bfr[1]);
                mma16816(acc[mi][nt], aL[mi][1], bfr[2], bfr[3]);
            }
        }
        __syncthreads();
    }

    // ---- epilogue: direct stores + bias ----
    const int r = lane >> 2, c2 = (lane & 3) * 2;
    #pragma unroll
    for (int mi = 0; mi < 2; mi++) {
        int row0 = m0 + mw * 32 + mi * 16 + r;
        int row1 = row0 + 8;
        #pragma unroll
        for (int nt = 0; nt < 8; nt++) {
            int gc = n0 + nw * 64 + nt * 8 + c2;
            float b0 = bias[gc], b1 = bias[gc + 1];
            float* p0; float* p1;
            if (MODE == 0) {
                int hh = gc >> 6, d = gc & 63;
                p0 = C + ((size_t)hh * SEQ + row0) * HD + d;
                p1 = C + ((size_t)hh * SEQ + row1) * HD + d;
            } else {
                p0 = C + (size_t)row0 * N + gc;
                p1 = C + (size_t)row1 * N + gc;
            }
            *(float2*)p0 = make_float2(acc[mi][nt][0] + b0, acc[mi][nt][1] + b1);
            *(float2*)p1 = make_float2(acc[mi][nt][2] + b0, acc[mi][nt][3] + b1);
        }
    }
}

// ---------------- elementwise ----------------
__global__ __launch_bounds__(256) void vp2_kernel(float* __restrict__ dst,
                                                  const float* __restrict__ a,
                                                  const float* __restrict__ b,
                                                  float c0, float c1)
{
    int i = blockIdx.x * 256 + threadIdx.x;
    float4 va = ((const float4*)a)[i];
    float4 vb = ((const float4*)b)[i];
    float4 o;
    o.x = c0 * va.x + c1 * vb.x; o.y = c0 * va.y + c1 * vb.y;
    o.z = c0 * va.z + c1 * vb.z; o.w = c0 * va.w + c1 * vb.w;
    ((float4*)dst)[i] = o;
}
__global__ __launch_bounds__(256) void axpy_kernel(float* __restrict__ dst,
                                                   const float* __restrict__ src, float c)
{
    int i = blockIdx.x * 256 + threadIdx.x;
    float4 v = ((const float4*)src)[i];
    float4 d = ((float4*)dst)[i];
    d.x = fmaf(c, v.x, d.x); d.y = fmaf(c, v.y, d.y);
    d.z = fmaf(c, v.z, d.z); d.w = fmaf(c, v.w, d.w);
    ((float4*)dst)[i] = d;
}

// ---------------- launch ----------------
extern "C" void kernel_launch(void* const* d_in, const int* in_sizes, int n_in,
                              void* d_out, int out_size)
{
    const float* X  = (const float*)d_in[0];
    const float* Wq = (const float*)d_in[1];
    const float* bq = (const float*)d_in[2];
    const float* Wk = (const float*)d_in[3];
    const float* bk = (const float*)d_in[4];
    const float* Wv = (const float*)d_in[5];
    const float* bv = (const float*)d_in[6];
    const float* Wo = (const float*)d_in[7];
    const float* bo = (const float*)d_in[8];

    float *Qd, *Kd, *Vd, *ud, *u2d, *Vpd, *attnd;
    cudaGetSymbolAddress((void**)&Qd,    g_Q);
    cudaGetSymbolAddress((void**)&Kd,    g_K);
    cudaGetSymbolAddress((void**)&Vd,    g_V);
    cudaGetSymbolAddress((void**)&ud,    g_u);
    cudaGetSymbolAddress((void**)&u2d,   g_u2);
    cudaGetSymbolAddress((void**)&Vpd,   g_Vp);
    cudaGetSymbolAddress((void**)&attnd, g_attn);

    __nv_bfloat16 *bKnA, *bKnB, *bX, *bQh, *bQl, *bKh, *bKl, *bVh, *bVl;
    cudaGetSymbolAddress((void**)&bKnA, g_bKnA);
    cudaGetSymbolAddress((void**)&bKnB, g_bKnB);
    cudaGetSymbolAddress((void**)&bX,   g_bX);
    cudaGetSymbolAddress((void**)&bQh,  g_bQh);
    cudaGetSymbolAddress((void**)&bQl,  g_bQl);
    cudaGetSymbolAddress((void**)&bKh,  g_bKh);
    cudaGetSymbolAddress((void**)&bKl,  g_bKl);
    cudaGetSymbolAddress((void**)&bVh,  g_bVh);
    cudaGetSymbolAddress((void**)&bVl,  g_bVl);

    __nv_bfloat16 *bXh, *bXl, *bWqh, *bWql, *bWkh, *bWkl, *bWvh, *bWvl, *bWoh, *bWol, *bAh, *bAl;
    cudaGetSymbolAddress((void**)&bXh,  g_bXh);
    cudaGetSymbolAddress((void**)&bXl,  g_bXl);
    cudaGetSymbolAddress((void**)&bWqh, g_bWqh);
    cudaGetSymbolAddress((void**)&bWql, g_bWql);
    cudaGetSymbolAddress((void**)&bWkh, g_bWkh);
    cudaGetSymbolAddress((void**)&bWkl, g_bWkl);
    cudaGetSymbolAddress((void**)&bWvh, g_bWvh);
    cudaGetSymbolAddress((void**)&bWvl, g_bWvl);
    cudaGetSymbolAddress((void**)&bWoh, g_bWoh);
    cudaGetSymbolAddress((void**)&bWol, g_bWol);
    cudaGetSymbolAddress((void**)&bAh,  g_bAh);
    cudaGetSymbolAddress((void**)&bAl,  g_bAl);

    cudaFuncSetAttribute(attn_kernel<0>, cudaFuncAttributeMaxDynamicSharedMemorySize, SM_ATTN0);
    cudaFuncSetAttribute(attn_kernel<1>, cudaFuncAttributeMaxDynamicSharedMemorySize, SM_ATTN1);
    cudaFuncSetAttribute(gemm_raw_kernel<0>, cudaFuncAttributeMaxDynamicSharedMemorySize, GSM);
    cudaFuncSetAttribute(gemm_raw_kernel<1>, cudaFuncAttributeMaxDynamicSharedMemorySize, GSM);

    const float scl = 0.125f;
    const int NB  = (TOT / 4) / 256;            // 2M-elem float4 grid
    const int NBW = (EMB * EMB / 4) / 256;      // 1M-elem float4 grid
    dim3 gattn(SEQ / 64, NHEADS);

    // 0) pre-convert GEMM operands (hi/lo)
    cvt_kernel<1><<<NB,  256>>>(X,  bXh,  bXl,  1.0f);
    cvt_kernel<1><<<NBW, 256>>>(Wq, bWqh, bWql, 1.0f);
    cvt_kernel<1><<<NBW, 256>>>(Wk, bWkh, bWkl, 1.0f);
    cvt_kernel<1><<<NBW, 256>>>(Wv, bWvh, bWvl, 1.0f);
    cvt_kernel<1><<<NBW, 256>>>(Wo, bWoh, bWol, 1.0f);

    // 1) fused Q/K/V projections (head-split outputs)
    dim3 gqkv(EMB / 128, SEQ / 128, 3);
    gemm_raw_kernel<0><<<gqkv, 256, GSM>>>(bXh, bXl,
                                           bWqh, bWql, bq, Qd,
                                           bWkh, bWkl, bk, Kd,
                                           bWvh, bWvl, bv, Vd,
                                           SEQ, EMB, EMB);

    // 2) fused normalize + convert
    knorm_cvt_kernel<<<(NHEADS * SEQ) / 8, 256>>>(Kd, bKnA, bKnB, scl);
    cvt_kernel<0><<<NB, 256>>>(Vd, bX, nullptr, 1.0f);

    // 3) diffusion: V' = 0.98*(V + a*u1 + a^2*u2)
    attn_kernel<0><<<gattn, 128, SM_ATTN0>>>(bKnA, nullptr, bKnB, nullptr, bX, nullptr, ud, 0);
    vp2_kernel<<<NB, 256>>>(Vpd, Vd, ud, 0.98f, 0.98f * 0.02f);

    cvt_kernel<0><<<NB, 256>>>(ud, bX, nullptr, 1.0f);
    attn_kernel<0><<<gattn, 128, SM_ATTN0>>>(bKnA, nullptr, bKnB, nullptr, bX, nullptr, u2d, 0);
    axpy_kernel<<<NB, 256>>>(Vpd, u2d, 0.98f * 0.0004f);

    // 4) final attention (split-3)
    cvt_kernel<1><<<NB, 256>>>(Qd,  bQh, bQl, scl);
    cvt_kernel<1><<<NB, 256>>>(Kd,  bKh, bKl, 1.0f);
    cvt_kernel<1><<<NB, 256>>>(Vpd, bVh, bVl, 1.0f);
    attn_kernel<1><<<gattn, 128, SM_ATTN1>>>(bQh, bQl, bKh, bKl, bVh, bVl, attnd, 1);

    // 5) output projection -> d_out
    cvt_kernel<1><<<NB, 256>>>(attnd, bAh, bAl, 1.0f);
    dim3 go(EMB / 128, SEQ / 128, 1);
    gemm_raw_kernel<1><<<go, 256, GSM>>>(bAh, bAl,
                                         bWoh, bWol, bo, (float*)d_out,
                                         bWoh, bWol, bo, (float*)d_out,
                                         bWoh, bWol, bo, (float*)d_out,
                                         SEQ, EMB, EMB);
}